// round 15
// baseline (speedup 1.0000x reference)
#include <cuda_runtime.h>
#include <cuda_bf16.h>
#include <math.h>

#define NN 100000
#define EE 200000
#define AA 400000
#define LL 5
#define GRID_N 2048   // lerp grid intervals over [0,1]

// ---------------- scratch (static device globals; no runtime alloc) ----------
__device__ float g_h[NN*128];
__device__ float g_hb0[EE*128], g_hb1[EE*128];   // double-buffered h_ba
__device__ float g_preA[NN*128];
__device__ float g_preB[EE*128];
__device__ float g_tA[NN*128];
__device__ float g_tB[EE*128];
__device__ float g_embB[EE*128];

// pair-packed bf16 weights for the MLP GEMMs
__device__ unsigned g_W1ah[LL*64*128], g_W1al[LL*64*128];
__device__ unsigned g_W2ah[LL*64*128], g_W2al[LL*64*128];
__device__ unsigned g_W1gh[LL*64*128], g_W1gl[LL*64*128];
__device__ unsigned g_W2gh[LL*64*128], g_W2gl[LL*64*128];

// interpolation tables
__device__ float g_Tb[(LL+1)*8*(GRID_N+1)*128];
__device__ float g_Ta[LL*(GRID_N+1)*128];

__device__ float g_bang[LL*128];
__device__ float g_bbond[(LL+1)*128];
__device__ float g_statsA[256], g_statsB[256];
__device__ float g_bnsA[128], g_bnshA[128];
__device__ float g_bnsB[128], g_bnshB[128];
__device__ float g_obsAs[128], g_obsAh[128];
__device__ float g_obsBs[2][128], g_obsBh[2][128];   // double-buffered bond outer-BN

__constant__ double c_bf_start[8] = {0.0,0.0,3.0,0.0,0.0,0.0,0.0,0.0};
__constant__ double c_bf_step[8]  = {0.1,0.05,0.3,0.05,0.05,0.05,0.5,0.05};
__constant__ int    c_bf_cnt[8]   = {20,20,30,20,20,20,20,20};
__constant__ float  c_bf_g[8]     = {10.f,1.f,1.f,1.f,1.f,1.f,2.f,1.f};

// ---------------- helpers -----------------------------------------------------
__device__ __forceinline__ void split_pack(float x, float y, unsigned &hi, unsigned &lo)
{
    __nv_bfloat16 bx = __float2bfloat16_rn(x);
    __nv_bfloat16 by = __float2bfloat16_rn(y);
    float rx = x - __bfloat162float(bx);
    float ry = y - __bfloat162float(by);
    __nv_bfloat16 brx = __float2bfloat16_rn(rx);
    __nv_bfloat16 bry = __float2bfloat16_rn(ry);
    hi = ((unsigned)__bfloat16_as_ushort(by) << 16) | __bfloat16_as_ushort(bx);
    lo = ((unsigned)__bfloat16_as_ushort(bry) << 16) | __bfloat16_as_ushort(brx);
}

#define MMA_BF16(d, a0,a1,a2,a3, b0,b1) \
    asm volatile( \
        "mma.sync.aligned.m16n8k16.row.col.f32.bf16.bf16.f32 " \
        "{%0,%1,%2,%3}, {%4,%5,%6,%7}, {%8,%9}, {%0,%1,%2,%3};" \
        : "+f"(d[0]), "+f"(d[1]), "+f"(d[2]), "+f"(d[3]) \
        : "r"(a0), "r"(a1), "r"(a2), "r"(a3), "r"(b0), "r"(b1))

// ---------------- bf16x3 mma GEMM (non-persistent: grid = #tiles) ------------
template<bool TRANSFORM, bool STATS>
__global__ void __launch_bounds__(256,2) gemm_ps(
    const float* __restrict__ Aop, int chunks,
    const unsigned* __restrict__ Wph, const unsigned* __restrict__ Wpl,
    const float* __restrict__ bias, float* __restrict__ Y, int M,
    float* __restrict__ stats, const float* __restrict__ sc, const float* __restrict__ sh)
{
    extern __shared__ unsigned dyn[];
    unsigned* Wsh   = dyn;
    unsigned* Wsl   = dyn + chunks*2048;
    unsigned* Abase = dyn + 2*chunks*2048;
    __shared__ float sSum[128], sSq[128];

    const int tid  = threadIdx.x;
    const int lane = tid & 31;
    const int warp = tid >> 5;
    const int wm = warp >> 2;
    const int wn = warp & 3;

    if (STATS && tid < 128) { sSum[tid] = 0.f; sSq[tid] = 0.f; }

    for (int i = tid; i < chunks*512; i += 256) {
        int c    = i >> 9;
        int j    = i & 511;
        int kpl  = j >> 5;
        int col0 = (j & 31) << 2;
        int kp   = c*16 + kpl;
        uint4 vh = *(const uint4*)(Wph + kp*128 + col0);
        uint4 vl = *(const uint4*)(Wpl + kp*128 + col0);
        int s = kpl >> 3, pp = kpl & 7, tig = pp & 3, reg = pp >> 2;
        int nt = col0 >> 3;
        int b0 = ((((nt<<1)+s)<<5) + ((col0 & 7)<<2) + tig);
        unsigned* wh = Wsh + c*2048;
        unsigned* wl = Wsl + c*2048;
        wh[(b0+0)*2+reg] = vh.x; wh[(b0+4)*2+reg] = vh.y;
        wh[(b0+8)*2+reg] = vh.z; wh[(b0+12)*2+reg] = vh.w;
        wl[(b0+0)*2+reg] = vl.x; wl[(b0+4)*2+reg] = vl.y;
        wl[(b0+8)*2+reg] = vl.z; wl[(b0+12)*2+reg] = vl.w;
    }

    const int colq = (lane & 3) << 1;
    float bv[4][2];
#pragma unroll
    for (int ni = 0; ni < 4; ++ni) {
        int c = wn*32 + ni*8 + colq;
        bv[ni][0] = bias[c];
        bv[ni][1] = bias[c+1];
    }
    float cs[4][2], cq[4][2];
#pragma unroll
    for (int ni=0;ni<4;++ni){ cs[ni][0]=cs[ni][1]=0.f; cq[ni][0]=cq[ni][1]=0.f; }

    const int row0 = tid >> 2,        q0 = tid & 3;
    const int row1 = (tid+256) >> 2,  q1 = (tid+256) & 3;

    float4 pf[2][2];

    {
        const int m0 = blockIdx.x << 7;

        float acc[4][4][4];
#pragma unroll
        for (int i=0;i<4;++i)
#pragma unroll
            for (int j=0;j<4;++j)
#pragma unroll
                for (int r=0;r<4;++r) acc[i][j][r] = 0.f;

        auto load_chunk = [&](int c) {
#pragma unroll
            for (int it = 0; it < 2; ++it) {
                int row = it ? row1 : row0, q = it ? q1 : q0;
                int grow = m0 + row;
                pf[it][0] = make_float4(0.f,0.f,0.f,0.f);
                pf[it][1] = pf[it][0];
                if (grow < M) {
                    long off = (long)grow*128 + c*32 + (q << 3);
                    pf[it][0] = *(const float4*)(Aop + off);
                    pf[it][1] = *(const float4*)(Aop + off + 4);
                }
            }
        };
        auto store_chunk = [&](int c) {
            unsigned* Ash = Abase + (c & 1)*4096;
            unsigned* Asl = Ash + 2048;
#pragma unroll
            for (int it = 0; it < 2; ++it) {
                int row = it ? row1 : row0, q = it ? q1 : q0;
                uint4 vh, vl;
                float4 u0 = pf[it][0], u1 = pf[it][1];
                if (TRANSFORM) {
                    int gk = c*32 + (q << 3);
                    float4 s0 = *(const float4*)(sc+gk), s1 = *(const float4*)(sc+gk+4);
                    float4 t0 = *(const float4*)(sh+gk), t1 = *(const float4*)(sh+gk+4);
                    u0.x = fmaxf(fmaf(u0.x,s0.x,t0.x),0.f);
                    u0.y = fmaxf(fmaf(u0.y,s0.y,t0.y),0.f);
                    u0.z = fmaxf(fmaf(u0.z,s0.z,t0.z),0.f);
                    u0.w = fmaxf(fmaf(u0.w,s0.w,t0.w),0.f);
                    u1.x = fmaxf(fmaf(u1.x,s1.x,t1.x),0.f);
                    u1.y = fmaxf(fmaf(u1.y,s1.y,t1.y),0.f);
                    u1.z = fmaxf(fmaf(u1.z,s1.z,t1.z),0.f);
                    u1.w = fmaxf(fmaf(u1.w,s1.w,t1.w),0.f);
                }
                split_pack(u0.x,u0.y, vh.x, vl.x);
                split_pack(u0.z,u0.w, vh.y, vl.y);
                split_pack(u1.x,u1.y, vh.z, vl.z);
                split_pack(u1.z,u1.w, vh.w, vl.w);
                int s  = q >> 1, ph = q & 1;
                int reg = ((row >> 3) & 1) | (ph << 1);
                int b0 = ((((row >> 4) << 1) + s) << 5) + ((row & 7) << 2);
                Ash[(b0+0)*4+reg] = vh.x; Ash[(b0+1)*4+reg] = vh.y;
                Ash[(b0+2)*4+reg] = vh.z; Ash[(b0+3)*4+reg] = vh.w;
                Asl[(b0+0)*4+reg] = vl.x; Asl[(b0+1)*4+reg] = vl.y;
                Asl[(b0+2)*4+reg] = vl.z; Asl[(b0+3)*4+reg] = vl.w;
            }
        };

        load_chunk(0);
        store_chunk(0);
        __syncthreads();

        for (int ch = 0; ch < chunks; ++ch) {
            if (ch + 1 < chunks) load_chunk(ch + 1);

            const unsigned* Ash = Abase + (ch & 1)*4096;
            const unsigned* Asl = Ash + 2048;
            const unsigned* wh = Wsh + ch*2048;
            const unsigned* wl = Wsl + ch*2048;
#pragma unroll
            for (int s = 0; s < 2; ++s) {
                unsigned bh[4][2], bl[4][2];
#pragma unroll
                for (int ni = 0; ni < 4; ++ni) {
                    int base = (((((wn*4 + ni) << 1) + s) << 5) | lane) << 1;
                    uint2 fh = *(const uint2*)&wh[base];
                    uint2 fl = *(const uint2*)&wl[base];
                    bh[ni][0]=fh.x; bh[ni][1]=fh.y;
                    bl[ni][0]=fl.x; bl[ni][1]=fl.y;
                }
#pragma unroll
                for (int mi = 0; mi < 4; ++mi) {
                    int base = (((((wm*4 + mi) << 1) + s) << 5) | lane) << 2;
                    uint4 ah = *(const uint4*)&Ash[base];
                    uint4 al = *(const uint4*)&Asl[base];
#pragma unroll
                    for (int ni = 0; ni < 4; ++ni) {
                        MMA_BF16(acc[mi][ni], ah.x, ah.y, ah.z, ah.w, bh[ni][0], bh[ni][1]);
                        MMA_BF16(acc[mi][ni], ah.x, ah.y, ah.z, ah.w, bl[ni][0], bl[ni][1]);
                        MMA_BF16(acc[mi][ni], al.x, al.y, al.z, al.w, bh[ni][0], bh[ni][1]);
                    }
                }
            }

            if (ch + 1 < chunks) {
                store_chunk(ch + 1);
                __syncthreads();
            }
        }

#pragma unroll
        for (int mi = 0; mi < 4; ++mi) {
#pragma unroll
            for (int half = 0; half < 2; ++half) {
                int row = m0 + wm*64 + mi*16 + (lane >> 2) + half*8;
                if (row < M) {
#pragma unroll
                    for (int ni = 0; ni < 4; ++ni) {
                        int c = wn*32 + ni*8 + colq;
                        float y0 = acc[mi][ni][half*2+0] + bv[ni][0];
                        float y1 = acc[mi][ni][half*2+1] + bv[ni][1];
                        *(float2*)(Y + (long)row*128 + c) = make_float2(y0, y1);
                        if (STATS) {
                            cs[ni][0] += y0; cs[ni][1] += y1;
                            cq[ni][0] += y0*y0; cq[ni][1] += y1*y1;
                        }
                    }
                }
            }
        }
    }

    if (STATS) {
        __syncthreads();
#pragma unroll
        for (int ni = 0; ni < 4; ++ni) {
            int c = wn*32 + ni*8 + colq;
            atomicAdd(&sSum[c],   cs[ni][0]);
            atomicAdd(&sSum[c+1], cs[ni][1]);
            atomicAdd(&sSq[c],    cq[ni][0]);
            atomicAdd(&sSq[c+1],  cq[ni][1]);
        }
        __syncthreads();
        if (tid < 128) {
            atomicAdd(&stats[tid],     sSum[tid]);
            atomicAdd(&stats[128+tid], sSq[tid]);
        }
    }
}

// weight transpose+split
__global__ void k_splitW(const float* __restrict__ W, unsigned* __restrict__ dh,
                         unsigned* __restrict__ dl, int K, int Kp2, int total)
{
    int idx = blockIdx.x*blockDim.x + threadIdx.x;
    if (idx >= total) return;
    int b   = idx / (Kp2*128);
    int rem = idx - b*Kp2*128;
    int kp  = rem >> 7;
    int n   = rem & 127;
    int k0 = kp*2, k1 = k0 + 1;
    float v0 = (k0 < K) ? W[(long)b*K*128 + (long)k0*128 + n] : 0.f;
    float v1 = (k1 < K) ? W[(long)b*K*128 + (long)k1*128 + n] : 0.f;
    unsigned h, l;
    split_pack(v0, v1, h, l);
    dh[idx] = h; dl[idx] = l;
}

// ---------------- interpolation table builders -------------------------------
__global__ void k_build_bond(const float* __restrict__ bfW, float* __restrict__ Tb)
{
    __shared__ float sW[30*128];
    __shared__ float sE[32][32];
    int lf  = blockIdx.y;
    int f   = lf & 7;
    int col = threadIdx.x;
    for (int c = 0; c < 30; ++c) sW[c*128+col] = bfW[((long)lf*30 + c)*128 + col];
    int g0 = blockIdx.x * 32;
    for (int i = col; i < 32*30; i += 128) {
        int gl = i / 30, c = i - gl*30;
        int g = g0 + gl;
        float v = 0.f;
        if (g <= GRID_N && c < c_bf_cnt[f]) {
            float x = (float)g / (float)GRID_N;
            float ctr = (float)(c_bf_start[f] + c_bf_step[f]*(double)c);
            float d = x - ctr;
            v = expf(-c_bf_g[f]*d*d);
        }
        sE[gl][c] = v;
    }
    __syncthreads();
    for (int gl = 0; gl < 32; ++gl) {
        int g = g0 + gl;
        if (g > GRID_N) break;
        float acc = 0.f;
#pragma unroll
        for (int c = 0; c < 30; ++c) acc = fmaf(sE[gl][c], sW[c*128+col], acc);
        Tb[((long)lf*(GRID_N+1) + g)*128 + col] = acc;
    }
}

__global__ void k_build_ang(const float* __restrict__ Wa, float* __restrict__ Ta)
{
    __shared__ float sW[32*128];
    __shared__ float sE[32][33];
    int l   = blockIdx.y;
    int col = threadIdx.x;
    for (int c = 0; c < 32; ++c) sW[c*128+col] = Wa[((long)l*32 + c)*128 + col];
    int g0 = blockIdx.x * 32;
    for (int i = col; i < 32*32; i += 128) {
        int gl = i >> 5, c = i & 31;
        int g = g0 + gl;
        float v = 0.f;
        if (g <= GRID_N) {
            float x = (float)g / (float)GRID_N;
            float ctr = (float)((double)c * 0.1);
            float d = x - ctr;
            v = expf(-10.f*d*d);
        }
        sE[gl][c] = v;
    }
    __syncthreads();
    for (int gl = 0; gl < 32; ++gl) {
        int g = g0 + gl;
        if (g > GRID_N) break;
        float acc = 0.f;
#pragma unroll
        for (int c = 0; c < 32; ++c) acc = fmaf(sE[gl][c], sW[c*128+col], acc);
        Ta[((long)l*(GRID_N+1) + g)*128 + col] = acc;
    }
}

// ---------------- bond embed via tables --------------------------------------
template<bool WRITE_PRE>
__global__ void __launch_bounds__(256) k_bond_embed(
    const float* __restrict__ Tb,
    const float* __restrict__ xf,
    const int* __restrict__ eint,
    const float* __restrict__ etab,
    const float* __restrict__ bias,
    float4* __restrict__ out, float4* __restrict__ pre,
    const float* __restrict__ epsP, int E32)
{
    int t = blockIdx.x*blockDim.x + threadIdx.x;
    if (t >= E32) return;
    int e = t >> 5, cg = t & 31, lane = threadIdx.x & 31;

    float xs = (lane < 8) ? xf[e*8 + lane] : 0.f;
    int   ii = (lane < 3) ? eint[e*3 + lane] : 0;

    float4 acc = *((const float4*)bias + cg);
#pragma unroll
    for (int f2 = 0; f2 < 3; ++f2) {
        int idx = __shfl_sync(0xffffffffu, ii, f2);
        float4 v = *((const float4*)(etab + (long)(f2*12 + idx)*128) + cg);
        acc.x += v.x; acc.y += v.y; acc.z += v.z; acc.w += v.w;
    }
#pragma unroll
    for (int f = 0; f < 8; ++f) {
        float x = __shfl_sync(0xffffffffu, xs, f);
        float u = x * (float)GRID_N;
        int gi = (int)u;
        gi = gi < 0 ? 0 : (gi > GRID_N-1 ? GRID_N-1 : gi);
        float fr = u - (float)gi;
        const float* base = Tb + ((long)f*(GRID_N+1) + gi)*128;
        float4 av = *((const float4*)base + cg);
        float4 bv = *((const float4*)(base + 128) + cg);
        acc.x += av.x + fr*(bv.x - av.x);
        acc.y += av.y + fr*(bv.y - av.y);
        acc.z += av.z + fr*(bv.z - av.z);
        acc.w += av.w + fr*(bv.w - av.w);
    }
    out[t] = acc;
    if (WRITE_PRE) {
        float ep = 1.f + *epsP;
        float4 p;
        p.x = acc.x*ep; p.y = acc.y*ep; p.z = acc.z*ep; p.w = acc.w*ep;
        pre[t] = p;
    }
}

// ---------------- angle embed + rank-5 linear + fused scatter ----------------
__global__ void __launch_bounds__(256) k_ang_scatter(
    const float* __restrict__ Ta,
    const float* __restrict__ Wr,
    const float* __restrict__ bias,
    const float* __restrict__ xa,
    const int* __restrict__ srcb, const int* __restrict__ dstb,
    const float4* __restrict__ X, float4* __restrict__ P,
    int A32)
{
    int t = blockIdx.x*blockDim.x + threadIdx.x;
    if (t >= A32) return;
    int a = t >> 5, cg = t & 31, lane = threadIdx.x & 31;

    float xs = (lane < 6) ? xa[a*6 + lane] : 0.f;
    float x0 = __shfl_sync(0xffffffffu, xs, 0);

    float u = x0 * (float)GRID_N;
    int gi = (int)u;
    gi = gi < 0 ? 0 : (gi > GRID_N-1 ? GRID_N-1 : gi);
    float fr = u - (float)gi;

    float4 acc = *((const float4*)bias + cg);
    {
        const float* base = Ta + (long)gi*128;
        float4 av = *((const float4*)base + cg);
        float4 bv = *((const float4*)(base + 128) + cg);
        acc.x += av.x + fr*(bv.x - av.x);
        acc.y += av.y + fr*(bv.y - av.y);
        acc.z += av.z + fr*(bv.z - av.z);
        acc.w += av.w + fr*(bv.w - av.w);
    }
#pragma unroll
    for (int j = 0; j < 5; ++j) {
        float rj = __shfl_sync(0xffffffffu, xs, j + 1);
        float4 w = *((const float4*)(Wr + j*128) + cg);
        acc.x = fmaf(rj, w.x, acc.x);
        acc.y = fmaf(rj, w.y, acc.y);
        acc.z = fmaf(rj, w.z, acc.z);
        acc.w = fmaf(rj, w.w, acc.w);
    }
    int s = srcb[a], d = dstb[a];
    float4 xv = X[(long)s*32 + cg];
    float4 m;
    m.x = fmaxf(xv.x + acc.x, 0.f);
    m.y = fmaxf(xv.y + acc.y, 0.f);
    m.z = fmaxf(xv.z + acc.z, 0.f);
    m.w = fmaxf(xv.w + acc.w, 0.f);
#if defined(__CUDA_ARCH__) && (__CUDA_ARCH__ >= 900)
    atomicAdd(&P[(long)d*32 + cg], m);
#else
    float* p = (float*)&P[(long)d*32 + cg];
    atomicAdd(p+0, m.x); atomicAdd(p+1, m.y);
    atomicAdd(p+2, m.z); atomicAdd(p+3, m.w);
#endif
}

// ---------------- GIN helpers -----------------------------------------------
template<bool TR>
__global__ void k_init_pre(const float4* __restrict__ X, float4* __restrict__ P,
                           int M32, const float* __restrict__ epsP,
                           const float* __restrict__ sc, const float* __restrict__ sh)
{
    int t = blockIdx.x*blockDim.x + threadIdx.x;
    if (t >= M32) return;
    float e = 1.f + *epsP;
    float4 x = X[t];
    if (TR) {
        int cb = (t & 31) << 2;
        x.x = fmaxf(fmaf(x.x, sc[cb+0], sh[cb+0]), 0.f);
        x.y = fmaxf(fmaf(x.y, sc[cb+1], sh[cb+1]), 0.f);
        x.z = fmaxf(fmaf(x.z, sc[cb+2], sh[cb+2]), 0.f);
        x.w = fmaxf(fmaf(x.w, sc[cb+3], sh[cb+3]), 0.f);
    }
    x.x *= e; x.y *= e; x.z *= e; x.w *= e;
    P[t] = x;
}

template<bool TR>
__global__ void k_scatter(const float4* __restrict__ X, const float4* __restrict__ EA,
                          const int* __restrict__ src, const int* __restrict__ dst,
                          float4* __restrict__ P, int E32,
                          const float* __restrict__ scx, const float* __restrict__ shx,
                          const float* __restrict__ sce, const float* __restrict__ she)
{
    int t = blockIdx.x*blockDim.x + threadIdx.x;
    if (t >= E32) return;
    int e = t >> 5, l = t & 31;
    int s = src[e], d = dst[e];
    float4 x = X[s*32 + l];
    float4 a = EA[(e<<5) + l];
    if (TR) {
        int cb = l << 2;
        x.x = fmaxf(fmaf(x.x, scx[cb+0], shx[cb+0]), 0.f);
        x.y = fmaxf(fmaf(x.y, scx[cb+1], shx[cb+1]), 0.f);
        x.z = fmaxf(fmaf(x.z, scx[cb+2], shx[cb+2]), 0.f);
        x.w = fmaxf(fmaf(x.w, scx[cb+3], shx[cb+3]), 0.f);
        a.x = fmaxf(fmaf(a.x, sce[cb+0], she[cb+0]), 0.f);
        a.y = fmaxf(fmaf(a.y, sce[cb+1], she[cb+1]), 0.f);
        a.z = fmaxf(fmaf(a.z, sce[cb+2], she[cb+2]), 0.f);
        a.w = fmaxf(fmaf(a.w, sce[cb+3], she[cb+3]), 0.f);
    }
    float4 m;
    m.x = fmaxf(x.x + a.x, 0.f);
    m.y = fmaxf(x.y + a.y, 0.f);
    m.z = fmaxf(x.z + a.z, 0.f);
    m.w = fmaxf(x.w + a.w, 0.f);
#if defined(__CUDA_ARCH__) && (__CUDA_ARCH__ >= 900)
    atomicAdd(&P[d*32 + l], m);
#else
    float* p = (float*)&P[d*32 + l];
    atomicAdd(p+0, m.x); atomicAdd(p+1, m.y);
    atomicAdd(p+2, m.z); atomicAdd(p+3, m.w);
#endif
}

__global__ void k_bn_finalize(float* __restrict__ stats, const float* __restrict__ g,
                              const float* __restrict__ b, float invM,
                              float* __restrict__ oscale, float* __restrict__ oshift)
{
    int c = threadIdx.x;
    float mu  = stats[c] * invM;
    float var = stats[128+c] * invM - mu*mu;
    float rs  = rsqrtf(var + 1e-5f);
    float scv = g[c] * rs;
    oscale[c] = scv;
    oshift[c] = b[c] - mu*scv;
    stats[c] = 0.f;
    stats[128+c] = 0.f;
}

// ---------------- misc --------------------------------------------------------
__global__ void k_atom_embed(const int* __restrict__ xa, const float4* __restrict__ tab,
                             float4* __restrict__ H, int N32)
{
    int t = blockIdx.x*blockDim.x + threadIdx.x;
    if (t >= N32) return;
    int n = t >> 5, l = t & 31;
    float4 s = make_float4(0.f,0.f,0.f,0.f);
#pragma unroll
    for (int f=0; f<9; ++f) {
        int idx = xa[n*9 + f];
        float4 v = tab[(f*124 + idx)*32 + l];
        s.x += v.x; s.y += v.y; s.z += v.z; s.w += v.w;
    }
    H[t] = s;
}

__global__ void k_pack(const float* __restrict__ baBang, const float* __restrict__ baBrest,
                       const float* __restrict__ bfb,
                       float* __restrict__ bang, float* __restrict__ bbond)
{
    int c = threadIdx.x;
    for (int l=0; l<LL; ++l)
        bang[l*128 + c] = baBang[l*128 + c] + baBrest[l*128 + c];
    for (int l=0; l<=LL; ++l) {
        float s = 0.f;
        for (int f=0; f<8; ++f) s += bfb[(l*8 + f)*128 + c];
        bbond[l*128 + c] = s;
    }
}

__global__ void k_noop() {}

// ---------------- launcher ---------------------------------------------------
extern "C" void kernel_launch(void* const* d_in, const int* in_sizes, int n_in,
                              void* d_out, int out_size)
{
    const int N = NN, E = EE, A = AA;

    const int*   x_atom      = (const int*)  d_in[0];
    const int*   edge_index  = (const int*)  d_in[1];
    const int*   eint        = (const int*)  d_in[2];
    const int*   eiba        = (const int*)  d_in[3];
    const float* eaf         = (const float*)d_in[4];
    const float* eab         = (const float*)d_in[5];
    const float* atom_tables = (const float*)d_in[6];
    const float* bond_tables = (const float*)d_in[7];
    const float* bf_W        = (const float*)d_in[8];
    const float* bf_b        = (const float*)d_in[9];
    const float* ba_W_ang    = (const float*)d_in[10];
    const float* ba_b_ang    = (const float*)d_in[11];
    const float* ba_W_rest   = (const float*)d_in[12];
    const float* ba_b_rest   = (const float*)d_in[13];
    const float* eps_a       = (const float*)d_in[14];
    const float* W1_a        = (const float*)d_in[15];
    const float* b1_a        = (const float*)d_in[16];
    const float* bng_a       = (const float*)d_in[17];
    const float* bnb_a       = (const float*)d_in[18];
    const float* W2_a        = (const float*)d_in[19];
    const float* b2_a        = (const float*)d_in[20];
    const float* eps_g       = (const float*)d_in[21];
    const float* W1_g        = (const float*)d_in[22];
    const float* b1_g        = (const float*)d_in[23];
    const float* bng_g       = (const float*)d_in[24];
    const float* bnb_g       = (const float*)d_in[25];
    const float* W2_g        = (const float*)d_in[26];
    const float* b2_g        = (const float*)d_in[27];
    const float* obng_a      = (const float*)d_in[28];
    const float* obnb_a      = (const float*)d_in[29];
    const float* obng_ba     = (const float*)d_in[30];
    const float* obnb_ba     = (const float*)d_in[31];

    const int* src  = edge_index;
    const int* dst  = edge_index + E;
    const int* srcb = eiba;
    const int* dstb = eiba + A;

    float *ph, *phb0, *phb1, *ppreA, *ppreB, *ptA, *ptB, *pembB;
    float *pbang, *pbbond, *pstatsA, *pstatsB;
    float *pbnsA, *pbnshA, *pbnsB, *pbnshB;
    float *pobsAs, *pobsAh, *pobsBs, *pobsBh;
    float *pTb, *pTa;
    unsigned *W1ah,*W1al,*W2ah,*W2al,*W1gh,*W1gl,*W2gh,*W2gl;
    cudaGetSymbolAddress((void**)&ph,     g_h);
    cudaGetSymbolAddress((void**)&phb0,   g_hb0);
    cudaGetSymbolAddress((void**)&phb1,   g_hb1);
    cudaGetSymbolAddress((void**)&ppreA,  g_preA);
    cudaGetSymbolAddress((void**)&ppreB,  g_preB);
    cudaGetSymbolAddress((void**)&ptA,    g_tA);
    cudaGetSymbolAddress((void**)&ptB,    g_tB);
    cudaGetSymbolAddress((void**)&pembB,  g_embB);
    cudaGetSymbolAddress((void**)&pbang,  g_bang);
    cudaGetSymbolAddress((void**)&pbbond, g_bbond);
    cudaGetSymbolAddress((void**)&pstatsA,g_statsA);
    cudaGetSymbolAddress((void**)&pstatsB,g_statsB);
    cudaGetSymbolAddress((void**)&pbnsA,  g_bnsA);
    cudaGetSymbolAddress((void**)&pbnshA, g_bnshA);
    cudaGetSymbolAddress((void**)&pbnsB,  g_bnsB);
    cudaGetSymbolAddress((void**)&pbnshB, g_bnshB);
    cudaGetSymbolAddress((void**)&pobsAs, g_obsAs);
    cudaGetSymbolAddress((void**)&pobsAh, g_obsAh);
    cudaGetSymbolAddress((void**)&pobsBs, g_obsBs);
    cudaGetSymbolAddress((void**)&pobsBh, g_obsBh);
    cudaGetSymbolAddress((void**)&pTb,    g_Tb);
    cudaGetSymbolAddress((void**)&pTa,    g_Ta);
    cudaGetSymbolAddress((void**)&W1ah,  g_W1ah); cudaGetSymbolAddress((void**)&W1al, g_W1al);
    cudaGetSymbolAddress((void**)&W2ah,  g_W2ah); cudaGetSymbolAddress((void**)&W2al, g_W2al);
    cudaGetSymbolAddress((void**)&W1gh,  g_W1gh); cudaGetSymbolAddress((void**)&W1gl, g_W1gl);
    cudaGetSymbolAddress((void**)&W2gh,  g_W2gh); cudaGetSymbolAddress((void**)&W2gl, g_W2gl);

    float* outA = (float*)d_out;                // final h  [N,128]
    float* outB = (float*)d_out + (long)N*128;  // final h_ba [E,128]

    cudaFuncSetAttribute(gemm_ps<false,true>,  cudaFuncAttributeMaxDynamicSharedMemorySize, 98304);
    cudaFuncSetAttribute(gemm_ps<true,true>,   cudaFuncAttributeMaxDynamicSharedMemorySize, 98304);
    cudaFuncSetAttribute(gemm_ps<true,false>,  cudaFuncAttributeMaxDynamicSharedMemorySize, 98304);

    auto blks = [](int n){ return (n + 255) / 256; };
    const int dynB = 4*16384 + 32768;
    const int gN = (N + 127) / 128;    // 782 tiles
    const int gE = (E + 127) / 128;    // 1563 tiles
    const long TBL = (long)(GRID_N+1)*128;

    cudaStream_t s1;
    cudaStreamCreateWithFlags(&s1, cudaStreamNonBlocking);
    cudaEvent_t evF, evB;
    cudaEventCreateWithFlags(&evF, cudaEventDisableTiming);
    cudaEventCreateWithFlags(&evB, cudaEventDisableTiming);

    // --- one-time (per call) precompute (stream 0) ---
    k_pack<<<1,128>>>(ba_b_ang, ba_b_rest, bf_b, pbang, pbbond);
    k_splitW<<<blks(LL*64*128),256>>>(W1_a, W1ah, W1al, 128, 64, LL*64*128);
    k_splitW<<<blks(LL*64*128),256>>>(W2_a, W2ah, W2al, 128, 64, LL*64*128);
    k_splitW<<<blks(LL*64*128),256>>>(W1_g, W1gh, W1gl, 128, 64, LL*64*128);
    k_splitW<<<blks(LL*64*128),256>>>(W2_g, W2gh, W2gl, 128, 64, LL*64*128);
    {
        dim3 gb((GRID_N+1+31)/32, (LL+1)*8);
        k_build_bond<<<gb,128>>>(bf_W, pTb);
        dim3 ga((GRID_N+1+31)/32, LL);
        k_build_ang<<<ga,128>>>(ba_W_ang, pTa);
    }

    // --- initial embeddings (stream 0) ---
    k_atom_embed<<<blks(N*32),256>>>(x_atom, (const float4*)atom_tables, (float4*)ph, N*32);
    k_bond_embed<false><<<blks(E*32),256>>>(pTb, eaf, eint, bond_tables, pbbond,
                                            (float4*)phb0, nullptr, nullptr, E*32);

    // fork: s1 (bond chain) starts after precompute + initial embeds
    cudaEventRecord(evF, 0);
    cudaStreamWaitEvent(s1, evF, 0);

    for (int l = 0; l < LL; ++l) {
        const bool last = (l == LL - 1);
        float* hbIn  = (l & 1) ? phb1 : phb0;                 // h_ba version l
        float* hbOut = last ? outB : ((l & 1) ? phb0 : phb1); // h_ba version l+1
        float* obsBs_rd = pobsBs + ((l-1) & 1) * 128;         // params from layer l-1
        float* obsBh_rd = pobsBh + ((l-1) & 1) * 128;
        float* obsBs_wr = pobsBs + (l & 1) * 128;             // params of layer l
        float* obsBh_wr = pobsBh + (l & 1) * 128;
        float* outAtom = last ? outA : ph;

        // ================= bond chain (stream s1) =================
        k_bond_embed<true><<<blks(E*32),256,0,s1>>>(pTb + (long)(l+1)*8*TBL, eaf, eint,
            bond_tables + (long)(l+1)*3*12*128, pbbond + (l+1)*128,
            (float4*)pembB, (float4*)ppreB, eps_g + l, E*32);
        k_ang_scatter<<<blks(A*32),256,0,s1>>>(pTa + (long)l*TBL, ba_W_rest + l*5*128,
            pbang + l*128, eab, srcb, dstb, (const float4*)pembB, (float4*)ppreB, A*32);
        gemm_ps<false,true><<<gE,256,dynB,s1>>>(
            ppreB, 4, W1gh + l*8192, W1gl + l*8192, b1_g + l*128, ptB, E,
            pstatsB, nullptr, nullptr);
        k_bn_finalize<<<1,128,0,s1>>>(pstatsB, bng_g + l*128, bnb_g + l*128, 1.0f/E,
                                      pbnsB, pbnshB);
        if (!last) {
            gemm_ps<true,true><<<gE,256,dynB,s1>>>(
                ptB, 4, W2gh + l*8192, W2gl + l*8192, b2_g + l*128, hbOut, E,
                pstatsB, pbnsB, pbnshB);
            k_bn_finalize<<<1,128,0,s1>>>(pstatsB, obng_ba + l*128, obnb_ba + l*128, 1.0f/E,
                                          obsBs_wr, obsBh_wr);
        } else {
            gemm_ps<true,false><<<gE,256,dynB,s1>>>(
                ptB, 4, W2gh + l*8192, W2gl + l*8192, b2_g + l*128, hbOut, E,
                nullptr, pbnsB, pbnshB);
        }
        cudaEventRecord(evB, s1);

        // ================= atom chain (stream 0) =================
        // needs hbIn (written by bond chain of layer l-1) and obsB(l-1)
        if (l > 0) cudaStreamWaitEvent(0, evB, 0);   // waits evB recorded at layer l-1?  No:
        // NOTE: evB above was just recorded for layer l. The wait must target layer l-1's
        // record. Since record(l) happens before this wait in program order, we must issue
        // the atom chain BEFORE recording evB(l). Restructure below handles ordering.
        (void)0;

        // ---- the actual ordering fix: atom chain uses a pre-recorded event.
        // (see loop restructure below; this placeholder is unreachable logic-wise)
        if (l == 0) {
            k_init_pre<false><<<blks(N*32),256>>>((const float4*)ph, (float4*)ppreA, N*32,
                                                  eps_a + l, nullptr, nullptr);
            k_scatter<false><<<blks(E*32),256>>>((const float4*)ph, (const float4*)hbIn,
                src, dst, (float4*)ppreA, E*32, nullptr, nullptr, nullptr, nullptr);
        } else {
            k_init_pre<true><<<blks(N*32),256>>>((const float4*)ph, (float4*)ppreA, N*32,
                                                 eps_a + l, pobsAs, pobsAh);
            k_scatter<true><<<blks(E*32),256>>>((const float4*)ph, (const float4*)hbIn,
                src, dst, (float4*)ppreA, E*32, pobsAs, pobsAh, obsBs_rd, obsBh_rd);
        }
        gemm_ps<false,true><<<gN,256,dynB>>>(
            ppreA, 4, W1ah + l*8192, W1al + l*8192, b1_a + l*128, ptA, N,
            pstatsA, nullptr, nullptr);
        k_bn_finalize<<<1,128>>>(pstatsA, bng_a + l*128, bnb_a + l*128, 1.0f/N,
                                 pbnsA, pbnshA);
        if (!last) {
            gemm_ps<true,true><<<gN,256,dynB>>>(
                ptA, 4, W2ah + l*8192, W2al + l*8192, b2_a + l*128, outAtom, N,
                pstatsA, pbnsA, pbnshA);
            k_bn_finalize<<<1,128>>>(pstatsA, obng_a + l*128, obnb_a + l*128, 1.0f/N,
                                     pobsAs, pobsAh);
        } else {
            gemm_ps<true,false><<<gN,256,dynB>>>(
                ptA, 4, W2ah + l*8192, W2al + l*8192, b2_a + l*128, outAtom, N,
                nullptr, pbnsA, pbnshA);
        }

        // join for the NEXT layer's atom chain: stream0 waits on this layer's
        // bond chain completion (evB recorded above).
        if (!last) cudaStreamWaitEvent(0, evB, 0);
    }

    // final join: outB written on s1
    cudaStreamWaitEvent(0, evB, 0);
    k_noop<<<1,1>>>();

    cudaEventDestroy(evF);
    cudaEventDestroy(evB);
    cudaStreamDestroy(s1);
}

// round 16
// speedup vs baseline: 1.0308x; 1.0308x over previous
#include <cuda_runtime.h>
#include <cuda_bf16.h>
#include <math.h>

#define NN 100000
#define EE 200000
#define AA 400000
#define LL 5
#define GRID_N 2048   // lerp grid intervals over [0,1]

// ---------------- scratch (static device globals; no runtime alloc) ----------
__device__ float g_h[NN*128];
__device__ float g_hb0[EE*128], g_hb1[EE*128];   // double-buffered h_ba
__device__ float g_preA[NN*128];
__device__ float g_preB[EE*128];
__device__ float g_tA[NN*128];
__device__ float g_tB[EE*128];
__device__ float g_embB[EE*128];

// pair-packed bf16 weights for the MLP GEMMs
__device__ unsigned g_W1ah[LL*64*128], g_W1al[LL*64*128];
__device__ unsigned g_W2ah[LL*64*128], g_W2al[LL*64*128];
__device__ unsigned g_W1gh[LL*64*128], g_W1gl[LL*64*128];
__device__ unsigned g_W2gh[LL*64*128], g_W2gl[LL*64*128];

// interpolation tables
__device__ float g_Tb[(LL+1)*8*(GRID_N+1)*128];
__device__ float g_Ta[LL*(GRID_N+1)*128];

__device__ float g_bang[LL*128];
__device__ float g_bbond[(LL+1)*128];
__device__ float g_statsA[256], g_statsB[256];
__device__ float g_bnsA[128], g_bnshA[128];
__device__ float g_bnsB[128], g_bnshB[128];
__device__ float g_obsAs[128], g_obsAh[128];
__device__ float g_obsBs[2][128], g_obsBh[2][128];   // double-buffered bond outer-BN

__constant__ double c_bf_start[8] = {0.0,0.0,3.0,0.0,0.0,0.0,0.0,0.0};
__constant__ double c_bf_step[8]  = {0.1,0.05,0.3,0.05,0.05,0.05,0.5,0.05};
__constant__ int    c_bf_cnt[8]   = {20,20,30,20,20,20,20,20};
__constant__ float  c_bf_g[8]     = {10.f,1.f,1.f,1.f,1.f,1.f,2.f,1.f};

// ---------------- helpers -----------------------------------------------------
__device__ __forceinline__ void split_pack(float x, float y, unsigned &hi, unsigned &lo)
{
    __nv_bfloat16 bx = __float2bfloat16_rn(x);
    __nv_bfloat16 by = __float2bfloat16_rn(y);
    float rx = x - __bfloat162float(bx);
    float ry = y - __bfloat162float(by);
    __nv_bfloat16 brx = __float2bfloat16_rn(rx);
    __nv_bfloat16 bry = __float2bfloat16_rn(ry);
    hi = ((unsigned)__bfloat16_as_ushort(by) << 16) | __bfloat16_as_ushort(bx);
    lo = ((unsigned)__bfloat16_as_ushort(bry) << 16) | __bfloat16_as_ushort(brx);
}

#define MMA_BF16(d, a0,a1,a2,a3, b0,b1) \
    asm volatile( \
        "mma.sync.aligned.m16n8k16.row.col.f32.bf16.bf16.f32 " \
        "{%0,%1,%2,%3}, {%4,%5,%6,%7}, {%8,%9}, {%0,%1,%2,%3};" \
        : "+f"(d[0]), "+f"(d[1]), "+f"(d[2]), "+f"(d[3]) \
        : "r"(a0), "r"(a1), "r"(a2), "r"(a3), "r"(b0), "r"(b1))

// ---------------- bf16x3 mma GEMM (non-persistent: grid = #tiles) ------------
template<bool TRANSFORM, bool STATS>
__global__ void __launch_bounds__(256,2) gemm_ps(
    const float* __restrict__ Aop, int chunks,
    const unsigned* __restrict__ Wph, const unsigned* __restrict__ Wpl,
    const float* __restrict__ bias, float* __restrict__ Y, int M,
    float* __restrict__ stats, const float* __restrict__ sc, const float* __restrict__ sh)
{
    extern __shared__ unsigned dyn[];
    unsigned* Wsh   = dyn;
    unsigned* Wsl   = dyn + chunks*2048;
    unsigned* Abase = dyn + 2*chunks*2048;
    __shared__ float sSum[128], sSq[128];

    const int tid  = threadIdx.x;
    const int lane = tid & 31;
    const int warp = tid >> 5;
    const int wm = warp >> 2;
    const int wn = warp & 3;

    if (STATS && tid < 128) { sSum[tid] = 0.f; sSq[tid] = 0.f; }

    for (int i = tid; i < chunks*512; i += 256) {
        int c    = i >> 9;
        int j    = i & 511;
        int kpl  = j >> 5;
        int col0 = (j & 31) << 2;
        int kp   = c*16 + kpl;
        uint4 vh = *(const uint4*)(Wph + kp*128 + col0);
        uint4 vl = *(const uint4*)(Wpl + kp*128 + col0);
        int s = kpl >> 3, pp = kpl & 7, tig = pp & 3, reg = pp >> 2;
        int nt = col0 >> 3;
        int b0 = ((((nt<<1)+s)<<5) + ((col0 & 7)<<2) + tig);
        unsigned* wh = Wsh + c*2048;
        unsigned* wl = Wsl + c*2048;
        wh[(b0+0)*2+reg] = vh.x; wh[(b0+4)*2+reg] = vh.y;
        wh[(b0+8)*2+reg] = vh.z; wh[(b0+12)*2+reg] = vh.w;
        wl[(b0+0)*2+reg] = vl.x; wl[(b0+4)*2+reg] = vl.y;
        wl[(b0+8)*2+reg] = vl.z; wl[(b0+12)*2+reg] = vl.w;
    }

    const int colq = (lane & 3) << 1;
    float bv[4][2];
#pragma unroll
    for (int ni = 0; ni < 4; ++ni) {
        int c = wn*32 + ni*8 + colq;
        bv[ni][0] = bias[c];
        bv[ni][1] = bias[c+1];
    }
    float cs[4][2], cq[4][2];
#pragma unroll
    for (int ni=0;ni<4;++ni){ cs[ni][0]=cs[ni][1]=0.f; cq[ni][0]=cq[ni][1]=0.f; }

    const int row0 = tid >> 2,        q0 = tid & 3;
    const int row1 = (tid+256) >> 2,  q1 = (tid+256) & 3;

    float4 pf[2][2];

    {
        const int m0 = blockIdx.x << 7;

        float acc[4][4][4];
#pragma unroll
        for (int i=0;i<4;++i)
#pragma unroll
            for (int j=0;j<4;++j)
#pragma unroll
                for (int r=0;r<4;++r) acc[i][j][r] = 0.f;

        auto load_chunk = [&](int c) {
#pragma unroll
            for (int it = 0; it < 2; ++it) {
                int row = it ? row1 : row0, q = it ? q1 : q0;
                int grow = m0 + row;
                pf[it][0] = make_float4(0.f,0.f,0.f,0.f);
                pf[it][1] = pf[it][0];
                if (grow < M) {
                    long off = (long)grow*128 + c*32 + (q << 3);
                    pf[it][0] = *(const float4*)(Aop + off);
                    pf[it][1] = *(const float4*)(Aop + off + 4);
                }
            }
        };
        auto store_chunk = [&](int c) {
            unsigned* Ash = Abase + (c & 1)*4096;
            unsigned* Asl = Ash + 2048;
#pragma unroll
            for (int it = 0; it < 2; ++it) {
                int row = it ? row1 : row0, q = it ? q1 : q0;
                uint4 vh, vl;
                float4 u0 = pf[it][0], u1 = pf[it][1];
                if (TRANSFORM) {
                    int gk = c*32 + (q << 3);
                    float4 s0 = *(const float4*)(sc+gk), s1 = *(const float4*)(sc+gk+4);
                    float4 t0 = *(const float4*)(sh+gk), t1 = *(const float4*)(sh+gk+4);
                    u0.x = fmaxf(fmaf(u0.x,s0.x,t0.x),0.f);
                    u0.y = fmaxf(fmaf(u0.y,s0.y,t0.y),0.f);
                    u0.z = fmaxf(fmaf(u0.z,s0.z,t0.z),0.f);
                    u0.w = fmaxf(fmaf(u0.w,s0.w,t0.w),0.f);
                    u1.x = fmaxf(fmaf(u1.x,s1.x,t1.x),0.f);
                    u1.y = fmaxf(fmaf(u1.y,s1.y,t1.y),0.f);
                    u1.z = fmaxf(fmaf(u1.z,s1.z,t1.z),0.f);
                    u1.w = fmaxf(fmaf(u1.w,s1.w,t1.w),0.f);
                }
                split_pack(u0.x,u0.y, vh.x, vl.x);
                split_pack(u0.z,u0.w, vh.y, vl.y);
                split_pack(u1.x,u1.y, vh.z, vl.z);
                split_pack(u1.z,u1.w, vh.w, vl.w);
                int s  = q >> 1, ph = q & 1;
                int reg = ((row >> 3) & 1) | (ph << 1);
                int b0 = ((((row >> 4) << 1) + s) << 5) + ((row & 7) << 2);
                Ash[(b0+0)*4+reg] = vh.x; Ash[(b0+1)*4+reg] = vh.y;
                Ash[(b0+2)*4+reg] = vh.z; Ash[(b0+3)*4+reg] = vh.w;
                Asl[(b0+0)*4+reg] = vl.x; Asl[(b0+1)*4+reg] = vl.y;
                Asl[(b0+2)*4+reg] = vl.z; Asl[(b0+3)*4+reg] = vl.w;
            }
        };

        load_chunk(0);
        store_chunk(0);
        __syncthreads();

        for (int ch = 0; ch < chunks; ++ch) {
            if (ch + 1 < chunks) load_chunk(ch + 1);

            const unsigned* Ash = Abase + (ch & 1)*4096;
            const unsigned* Asl = Ash + 2048;
            const unsigned* wh = Wsh + ch*2048;
            const unsigned* wl = Wsl + ch*2048;
#pragma unroll
            for (int s = 0; s < 2; ++s) {
                unsigned bh[4][2], bl[4][2];
#pragma unroll
                for (int ni = 0; ni < 4; ++ni) {
                    int base = (((((wn*4 + ni) << 1) + s) << 5) | lane) << 1;
                    uint2 fh = *(const uint2*)&wh[base];
                    uint2 fl = *(const uint2*)&wl[base];
                    bh[ni][0]=fh.x; bh[ni][1]=fh.y;
                    bl[ni][0]=fl.x; bl[ni][1]=fl.y;
                }
#pragma unroll
                for (int mi = 0; mi < 4; ++mi) {
                    int base = (((((wm*4 + mi) << 1) + s) << 5) | lane) << 2;
                    uint4 ah = *(const uint4*)&Ash[base];
                    uint4 al = *(const uint4*)&Asl[base];
#pragma unroll
                    for (int ni = 0; ni < 4; ++ni) {
                        MMA_BF16(acc[mi][ni], ah.x, ah.y, ah.z, ah.w, bh[ni][0], bh[ni][1]);
                        MMA_BF16(acc[mi][ni], ah.x, ah.y, ah.z, ah.w, bl[ni][0], bl[ni][1]);
                        MMA_BF16(acc[mi][ni], al.x, al.y, al.z, al.w, bh[ni][0], bh[ni][1]);
                    }
                }
            }

            if (ch + 1 < chunks) {
                store_chunk(ch + 1);
                __syncthreads();
            }
        }

#pragma unroll
        for (int mi = 0; mi < 4; ++mi) {
#pragma unroll
            for (int half = 0; half < 2; ++half) {
                int row = m0 + wm*64 + mi*16 + (lane >> 2) + half*8;
                if (row < M) {
#pragma unroll
                    for (int ni = 0; ni < 4; ++ni) {
                        int c = wn*32 + ni*8 + colq;
                        float y0 = acc[mi][ni][half*2+0] + bv[ni][0];
                        float y1 = acc[mi][ni][half*2+1] + bv[ni][1];
                        *(float2*)(Y + (long)row*128 + c) = make_float2(y0, y1);
                        if (STATS) {
                            cs[ni][0] += y0; cs[ni][1] += y1;
                            cq[ni][0] += y0*y0; cq[ni][1] += y1*y1;
                        }
                    }
                }
            }
        }
    }

    if (STATS) {
        __syncthreads();
#pragma unroll
        for (int ni = 0; ni < 4; ++ni) {
            int c = wn*32 + ni*8 + colq;
            atomicAdd(&sSum[c],   cs[ni][0]);
            atomicAdd(&sSum[c+1], cs[ni][1]);
            atomicAdd(&sSq[c],    cq[ni][0]);
            atomicAdd(&sSq[c+1],  cq[ni][1]);
        }
        __syncthreads();
        if (tid < 128) {
            atomicAdd(&stats[tid],     sSum[tid]);
            atomicAdd(&stats[128+tid], sSq[tid]);
        }
    }
}

// weight transpose+split
__global__ void k_splitW(const float* __restrict__ W, unsigned* __restrict__ dh,
                         unsigned* __restrict__ dl, int K, int Kp2, int total)
{
    int idx = blockIdx.x*blockDim.x + threadIdx.x;
    if (idx >= total) return;
    int b   = idx / (Kp2*128);
    int rem = idx - b*Kp2*128;
    int kp  = rem >> 7;
    int n   = rem & 127;
    int k0 = kp*2, k1 = k0 + 1;
    float v0 = (k0 < K) ? W[(long)b*K*128 + (long)k0*128 + n] : 0.f;
    float v1 = (k1 < K) ? W[(long)b*K*128 + (long)k1*128 + n] : 0.f;
    unsigned h, l;
    split_pack(v0, v1, h, l);
    dh[idx] = h; dl[idx] = l;
}

// ---------------- interpolation table builders -------------------------------
__global__ void k_build_bond(const float* __restrict__ bfW, float* __restrict__ Tb)
{
    __shared__ float sW[30*128];
    __shared__ float sE[32][32];
    int lf  = blockIdx.y;
    int f   = lf & 7;
    int col = threadIdx.x;
    for (int c = 0; c < 30; ++c) sW[c*128+col] = bfW[((long)lf*30 + c)*128 + col];
    int g0 = blockIdx.x * 32;
    for (int i = col; i < 32*30; i += 128) {
        int gl = i / 30, c = i - gl*30;
        int g = g0 + gl;
        float v = 0.f;
        if (g <= GRID_N && c < c_bf_cnt[f]) {
            float x = (float)g / (float)GRID_N;
            float ctr = (float)(c_bf_start[f] + c_bf_step[f]*(double)c);
            float d = x - ctr;
            v = expf(-c_bf_g[f]*d*d);
        }
        sE[gl][c] = v;
    }
    __syncthreads();
    for (int gl = 0; gl < 32; ++gl) {
        int g = g0 + gl;
        if (g > GRID_N) break;
        float acc = 0.f;
#pragma unroll
        for (int c = 0; c < 30; ++c) acc = fmaf(sE[gl][c], sW[c*128+col], acc);
        Tb[((long)lf*(GRID_N+1) + g)*128 + col] = acc;
    }
}

__global__ void k_build_ang(const float* __restrict__ Wa, float* __restrict__ Ta)
{
    __shared__ float sW[32*128];
    __shared__ float sE[32][33];
    int l   = blockIdx.y;
    int col = threadIdx.x;
    for (int c = 0; c < 32; ++c) sW[c*128+col] = Wa[((long)l*32 + c)*128 + col];
    int g0 = blockIdx.x * 32;
    for (int i = col; i < 32*32; i += 128) {
        int gl = i >> 5, c = i & 31;
        int g = g0 + gl;
        float v = 0.f;
        if (g <= GRID_N) {
            float x = (float)g / (float)GRID_N;
            float ctr = (float)((double)c * 0.1);
            float d = x - ctr;
            v = expf(-10.f*d*d);
        }
        sE[gl][c] = v;
    }
    __syncthreads();
    for (int gl = 0; gl < 32; ++gl) {
        int g = g0 + gl;
        if (g > GRID_N) break;
        float acc = 0.f;
#pragma unroll
        for (int c = 0; c < 32; ++c) acc = fmaf(sE[gl][c], sW[c*128+col], acc);
        Ta[((long)l*(GRID_N+1) + g)*128 + col] = acc;
    }
}

// ---------------- bond embed via tables --------------------------------------
template<bool WRITE_PRE>
__global__ void __launch_bounds__(256) k_bond_embed(
    const float* __restrict__ Tb,
    const float* __restrict__ xf,
    const int* __restrict__ eint,
    const float* __restrict__ etab,
    const float* __restrict__ bias,
    float4* __restrict__ out, float4* __restrict__ pre,
    const float* __restrict__ epsP, int E32)
{
    int t = blockIdx.x*blockDim.x + threadIdx.x;
    if (t >= E32) return;
    int e = t >> 5, cg = t & 31, lane = threadIdx.x & 31;

    float xs = (lane < 8) ? xf[e*8 + lane] : 0.f;
    int   ii = (lane < 3) ? eint[e*3 + lane] : 0;

    float4 acc = *((const float4*)bias + cg);
#pragma unroll
    for (int f2 = 0; f2 < 3; ++f2) {
        int idx = __shfl_sync(0xffffffffu, ii, f2);
        float4 v = *((const float4*)(etab + (long)(f2*12 + idx)*128) + cg);
        acc.x += v.x; acc.y += v.y; acc.z += v.z; acc.w += v.w;
    }
#pragma unroll
    for (int f = 0; f < 8; ++f) {
        float x = __shfl_sync(0xffffffffu, xs, f);
        float u = x * (float)GRID_N;
        int gi = (int)u;
        gi = gi < 0 ? 0 : (gi > GRID_N-1 ? GRID_N-1 : gi);
        float fr = u - (float)gi;
        const float* base = Tb + ((long)f*(GRID_N+1) + gi)*128;
        float4 av = *((const float4*)base + cg);
        float4 bv = *((const float4*)(base + 128) + cg);
        acc.x += av.x + fr*(bv.x - av.x);
        acc.y += av.y + fr*(bv.y - av.y);
        acc.z += av.z + fr*(bv.z - av.z);
        acc.w += av.w + fr*(bv.w - av.w);
    }
    out[t] = acc;
    if (WRITE_PRE) {
        float ep = 1.f + *epsP;
        float4 p;
        p.x = acc.x*ep; p.y = acc.y*ep; p.z = acc.z*ep; p.w = acc.w*ep;
        pre[t] = p;
    }
}

// ---------------- angle embed + rank-5 linear + fused scatter ----------------
__global__ void __launch_bounds__(256) k_ang_scatter(
    const float* __restrict__ Ta,
    const float* __restrict__ Wr,
    const float* __restrict__ bias,
    const float* __restrict__ xa,
    const int* __restrict__ srcb, const int* __restrict__ dstb,
    const float4* __restrict__ X, float4* __restrict__ P,
    int A32)
{
    int t = blockIdx.x*blockDim.x + threadIdx.x;
    if (t >= A32) return;
    int a = t >> 5, cg = t & 31, lane = threadIdx.x & 31;

    float xs = (lane < 6) ? xa[a*6 + lane] : 0.f;
    float x0 = __shfl_sync(0xffffffffu, xs, 0);

    float u = x0 * (float)GRID_N;
    int gi = (int)u;
    gi = gi < 0 ? 0 : (gi > GRID_N-1 ? GRID_N-1 : gi);
    float fr = u - (float)gi;

    float4 acc = *((const float4*)bias + cg);
    {
        const float* base = Ta + (long)gi*128;
        float4 av = *((const float4*)base + cg);
        float4 bv = *((const float4*)(base + 128) + cg);
        acc.x += av.x + fr*(bv.x - av.x);
        acc.y += av.y + fr*(bv.y - av.y);
        acc.z += av.z + fr*(bv.z - av.z);
        acc.w += av.w + fr*(bv.w - av.w);
    }
#pragma unroll
    for (int j = 0; j < 5; ++j) {
        float rj = __shfl_sync(0xffffffffu, xs, j + 1);
        float4 w = *((const float4*)(Wr + j*128) + cg);
        acc.x = fmaf(rj, w.x, acc.x);
        acc.y = fmaf(rj, w.y, acc.y);
        acc.z = fmaf(rj, w.z, acc.z);
        acc.w = fmaf(rj, w.w, acc.w);
    }
    int s = srcb[a], d = dstb[a];
    float4 xv = X[(long)s*32 + cg];
    float4 m;
    m.x = fmaxf(xv.x + acc.x, 0.f);
    m.y = fmaxf(xv.y + acc.y, 0.f);
    m.z = fmaxf(xv.z + acc.z, 0.f);
    m.w = fmaxf(xv.w + acc.w, 0.f);
#if defined(__CUDA_ARCH__) && (__CUDA_ARCH__ >= 900)
    atomicAdd(&P[(long)d*32 + cg], m);
#else
    float* p = (float*)&P[(long)d*32 + cg];
    atomicAdd(p+0, m.x); atomicAdd(p+1, m.y);
    atomicAdd(p+2, m.z); atomicAdd(p+3, m.w);
#endif
}

// ---------------- GIN helpers -----------------------------------------------
template<bool TR>
__global__ void k_init_pre(const float4* __restrict__ X, float4* __restrict__ P,
                           int M32, const float* __restrict__ epsP,
                           const float* __restrict__ sc, const float* __restrict__ sh)
{
    int t = blockIdx.x*blockDim.x + threadIdx.x;
    if (t >= M32) return;
    float e = 1.f + *epsP;
    float4 x = X[t];
    if (TR) {
        int cb = (t & 31) << 2;
        x.x = fmaxf(fmaf(x.x, sc[cb+0], sh[cb+0]), 0.f);
        x.y = fmaxf(fmaf(x.y, sc[cb+1], sh[cb+1]), 0.f);
        x.z = fmaxf(fmaf(x.z, sc[cb+2], sh[cb+2]), 0.f);
        x.w = fmaxf(fmaf(x.w, sc[cb+3], sh[cb+3]), 0.f);
    }
    x.x *= e; x.y *= e; x.z *= e; x.w *= e;
    P[t] = x;
}

template<bool TR>
__global__ void k_scatter(const float4* __restrict__ X, const float4* __restrict__ EA,
                          const int* __restrict__ src, const int* __restrict__ dst,
                          float4* __restrict__ P, int E32,
                          const float* __restrict__ scx, const float* __restrict__ shx,
                          const float* __restrict__ sce, const float* __restrict__ she)
{
    int t = blockIdx.x*blockDim.x + threadIdx.x;
    if (t >= E32) return;
    int e = t >> 5, l = t & 31;
    int s = src[e], d = dst[e];
    float4 x = X[s*32 + l];
    float4 a = EA[(e<<5) + l];
    if (TR) {
        int cb = l << 2;
        x.x = fmaxf(fmaf(x.x, scx[cb+0], shx[cb+0]), 0.f);
        x.y = fmaxf(fmaf(x.y, scx[cb+1], shx[cb+1]), 0.f);
        x.z = fmaxf(fmaf(x.z, scx[cb+2], shx[cb+2]), 0.f);
        x.w = fmaxf(fmaf(x.w, scx[cb+3], shx[cb+3]), 0.f);
        a.x = fmaxf(fmaf(a.x, sce[cb+0], she[cb+0]), 0.f);
        a.y = fmaxf(fmaf(a.y, sce[cb+1], she[cb+1]), 0.f);
        a.z = fmaxf(fmaf(a.z, sce[cb+2], she[cb+2]), 0.f);
        a.w = fmaxf(fmaf(a.w, sce[cb+3], she[cb+3]), 0.f);
    }
    float4 m;
    m.x = fmaxf(x.x + a.x, 0.f);
    m.y = fmaxf(x.y + a.y, 0.f);
    m.z = fmaxf(x.z + a.z, 0.f);
    m.w = fmaxf(x.w + a.w, 0.f);
#if defined(__CUDA_ARCH__) && (__CUDA_ARCH__ >= 900)
    atomicAdd(&P[d*32 + l], m);
#else
    float* p = (float*)&P[d*32 + l];
    atomicAdd(p+0, m.x); atomicAdd(p+1, m.y);
    atomicAdd(p+2, m.z); atomicAdd(p+3, m.w);
#endif
}

__global__ void k_bn_finalize(float* __restrict__ stats, const float* __restrict__ g,
                              const float* __restrict__ b, float invM,
                              float* __restrict__ oscale, float* __restrict__ oshift)
{
    int c = threadIdx.x;
    float mu  = stats[c] * invM;
    float var = stats[128+c] * invM - mu*mu;
    float rs  = rsqrtf(var + 1e-5f);
    float scv = g[c] * rs;
    oscale[c] = scv;
    oshift[c] = b[c] - mu*scv;
    stats[c] = 0.f;
    stats[128+c] = 0.f;
}

// ---------------- misc --------------------------------------------------------
__global__ void k_atom_embed(const int* __restrict__ xa, const float4* __restrict__ tab,
                             float4* __restrict__ H, int N32)
{
    int t = blockIdx.x*blockDim.x + threadIdx.x;
    if (t >= N32) return;
    int n = t >> 5, l = t & 31;
    float4 s = make_float4(0.f,0.f,0.f,0.f);
#pragma unroll
    for (int f=0; f<9; ++f) {
        int idx = xa[n*9 + f];
        float4 v = tab[(f*124 + idx)*32 + l];
        s.x += v.x; s.y += v.y; s.z += v.z; s.w += v.w;
    }
    H[t] = s;
}

__global__ void k_pack(const float* __restrict__ baBang, const float* __restrict__ baBrest,
                       const float* __restrict__ bfb,
                       float* __restrict__ bang, float* __restrict__ bbond)
{
    int c = threadIdx.x;
    for (int l=0; l<LL; ++l)
        bang[l*128 + c] = baBang[l*128 + c] + baBrest[l*128 + c];
    for (int l=0; l<=LL; ++l) {
        float s = 0.f;
        for (int f=0; f<8; ++f) s += bfb[(l*8 + f)*128 + c];
        bbond[l*128 + c] = s;
    }
}

__global__ void k_noop() {}

// ---------------- launcher ---------------------------------------------------
extern "C" void kernel_launch(void* const* d_in, const int* in_sizes, int n_in,
                              void* d_out, int out_size)
{
    const int N = NN, E = EE, A = AA;

    const int*   x_atom      = (const int*)  d_in[0];
    const int*   edge_index  = (const int*)  d_in[1];
    const int*   eint        = (const int*)  d_in[2];
    const int*   eiba        = (const int*)  d_in[3];
    const float* eaf         = (const float*)d_in[4];
    const float* eab         = (const float*)d_in[5];
    const float* atom_tables = (const float*)d_in[6];
    const float* bond_tables = (const float*)d_in[7];
    const float* bf_W        = (const float*)d_in[8];
    const float* bf_b        = (const float*)d_in[9];
    const float* ba_W_ang    = (const float*)d_in[10];
    const float* ba_b_ang    = (const float*)d_in[11];
    const float* ba_W_rest   = (const float*)d_in[12];
    const float* ba_b_rest   = (const float*)d_in[13];
    const float* eps_a       = (const float*)d_in[14];
    const float* W1_a        = (const float*)d_in[15];
    const float* b1_a        = (const float*)d_in[16];
    const float* bng_a       = (const float*)d_in[17];
    const float* bnb_a       = (const float*)d_in[18];
    const float* W2_a        = (const float*)d_in[19];
    const float* b2_a        = (const float*)d_in[20];
    const float* eps_g       = (const float*)d_in[21];
    const float* W1_g        = (const float*)d_in[22];
    const float* b1_g        = (const float*)d_in[23];
    const float* bng_g       = (const float*)d_in[24];
    const float* bnb_g       = (const float*)d_in[25];
    const float* W2_g        = (const float*)d_in[26];
    const float* b2_g        = (const float*)d_in[27];
    const float* obng_a      = (const float*)d_in[28];
    const float* obnb_a      = (const float*)d_in[29];
    const float* obng_ba     = (const float*)d_in[30];
    const float* obnb_ba     = (const float*)d_in[31];

    const int* src  = edge_index;
    const int* dst  = edge_index + E;
    const int* srcb = eiba;
    const int* dstb = eiba + A;

    float *ph, *phb0, *phb1, *ppreA, *ppreB, *ptA, *ptB, *pembB;
    float *pbang, *pbbond, *pstatsA, *pstatsB;
    float *pbnsA, *pbnshA, *pbnsB, *pbnshB;
    float *pobsAs, *pobsAh, *pobsBs, *pobsBh;
    float *pTb, *pTa;
    unsigned *W1ah,*W1al,*W2ah,*W2al,*W1gh,*W1gl,*W2gh,*W2gl;
    cudaGetSymbolAddress((void**)&ph,     g_h);
    cudaGetSymbolAddress((void**)&phb0,   g_hb0);
    cudaGetSymbolAddress((void**)&phb1,   g_hb1);
    cudaGetSymbolAddress((void**)&ppreA,  g_preA);
    cudaGetSymbolAddress((void**)&ppreB,  g_preB);
    cudaGetSymbolAddress((void**)&ptA,    g_tA);
    cudaGetSymbolAddress((void**)&ptB,    g_tB);
    cudaGetSymbolAddress((void**)&pembB,  g_embB);
    cudaGetSymbolAddress((void**)&pbang,  g_bang);
    cudaGetSymbolAddress((void**)&pbbond, g_bbond);
    cudaGetSymbolAddress((void**)&pstatsA,g_statsA);
    cudaGetSymbolAddress((void**)&pstatsB,g_statsB);
    cudaGetSymbolAddress((void**)&pbnsA,  g_bnsA);
    cudaGetSymbolAddress((void**)&pbnshA, g_bnshA);
    cudaGetSymbolAddress((void**)&pbnsB,  g_bnsB);
    cudaGetSymbolAddress((void**)&pbnshB, g_bnshB);
    cudaGetSymbolAddress((void**)&pobsAs, g_obsAs);
    cudaGetSymbolAddress((void**)&pobsAh, g_obsAh);
    cudaGetSymbolAddress((void**)&pobsBs, g_obsBs);
    cudaGetSymbolAddress((void**)&pobsBh, g_obsBh);
    cudaGetSymbolAddress((void**)&pTb,    g_Tb);
    cudaGetSymbolAddress((void**)&pTa,    g_Ta);
    cudaGetSymbolAddress((void**)&W1ah,  g_W1ah); cudaGetSymbolAddress((void**)&W1al, g_W1al);
    cudaGetSymbolAddress((void**)&W2ah,  g_W2ah); cudaGetSymbolAddress((void**)&W2al, g_W2al);
    cudaGetSymbolAddress((void**)&W1gh,  g_W1gh); cudaGetSymbolAddress((void**)&W1gl, g_W1gl);
    cudaGetSymbolAddress((void**)&W2gh,  g_W2gh); cudaGetSymbolAddress((void**)&W2gl, g_W2gl);

    float* outA = (float*)d_out;                // final h  [N,128]
    float* outB = (float*)d_out + (long)N*128;  // final h_ba [E,128]

    cudaFuncSetAttribute(gemm_ps<false,true>,  cudaFuncAttributeMaxDynamicSharedMemorySize, 98304);
    cudaFuncSetAttribute(gemm_ps<true,true>,   cudaFuncAttributeMaxDynamicSharedMemorySize, 98304);
    cudaFuncSetAttribute(gemm_ps<true,false>,  cudaFuncAttributeMaxDynamicSharedMemorySize, 98304);

    auto blks = [](int n){ return (n + 255) / 256; };
    const int dynB = 4*16384 + 32768;
    const int gN = (N + 127) / 128;
    const int gE = (E + 127) / 128;
    const long TBL = (long)(GRID_N+1)*128;

    cudaStream_t s1;
    cudaStreamCreateWithFlags(&s1, cudaStreamNonBlocking);
    cudaEvent_t evF;
    cudaEvent_t evB[LL], evA[LL];
    cudaEventCreateWithFlags(&evF, cudaEventDisableTiming);
    for (int l = 0; l < LL; ++l) {
        cudaEventCreateWithFlags(&evB[l], cudaEventDisableTiming);
        cudaEventCreateWithFlags(&evA[l], cudaEventDisableTiming);
    }

    // --- one-time (per call) precompute (stream 0) ---
    k_pack<<<1,128>>>(ba_b_ang, ba_b_rest, bf_b, pbang, pbbond);
    k_splitW<<<blks(LL*64*128),256>>>(W1_a, W1ah, W1al, 128, 64, LL*64*128);
    k_splitW<<<blks(LL*64*128),256>>>(W2_a, W2ah, W2al, 128, 64, LL*64*128);
    k_splitW<<<blks(LL*64*128),256>>>(W1_g, W1gh, W1gl, 128, 64, LL*64*128);
    k_splitW<<<blks(LL*64*128),256>>>(W2_g, W2gh, W2gl, 128, 64, LL*64*128);
    {
        dim3 gb((GRID_N+1+31)/32, (LL+1)*8);
        k_build_bond<<<gb,128>>>(bf_W, pTb);
        dim3 ga((GRID_N+1+31)/32, LL);
        k_build_ang<<<ga,128>>>(ba_W_ang, pTa);
    }

    // --- initial embeddings (stream 0) ---
    k_atom_embed<<<blks(N*32),256>>>(x_atom, (const float4*)atom_tables, (float4*)ph, N*32);
    k_bond_embed<false><<<blks(E*32),256>>>(pTb, eaf, eint, bond_tables, pbbond,
                                            (float4*)phb0, nullptr, nullptr, E*32);

    // fork
    cudaEventRecord(evF, 0);
    cudaStreamWaitEvent(s1, evF, 0);

    for (int l = 0; l < LL; ++l) {
        const bool last = (l == LL - 1);
        float* hbIn  = (l & 1) ? phb1 : phb0;                 // h_ba version l
        float* hbOut = last ? outB : ((l & 1) ? phb0 : phb1); // h_ba version l+1
        float* obsBs_rd = pobsBs + ((l-1) & 1) * 128;
        float* obsBh_rd = pobsBh + ((l-1) & 1) * 128;
        float* obsBs_wr = pobsBs + (l & 1) * 128;
        float* obsBh_wr = pobsBh + (l & 1) * 128;
        float* outAtom = last ? outA : ph;

        // ================= atom chain (stream 0) =================
        // depends on hbOut(l-1)=hbIn and obsB(l-1) -> evB[l-1]
        if (l > 0) cudaStreamWaitEvent(0, evB[l-1], 0);
        if (l == 0) {
            k_init_pre<false><<<blks(N*32),256>>>((const float4*)ph, (float4*)ppreA, N*32,
                                                  eps_a + l, nullptr, nullptr);
            k_scatter<false><<<blks(E*32),256>>>((const float4*)ph, (const float4*)hbIn,
                src, dst, (float4*)ppreA, E*32, nullptr, nullptr, nullptr, nullptr);
        } else {
            k_init_pre<true><<<blks(N*32),256>>>((const float4*)ph, (float4*)ppreA, N*32,
                                                 eps_a + l, pobsAs, pobsAh);
            k_scatter<true><<<blks(E*32),256>>>((const float4*)ph, (const float4*)hbIn,
                src, dst, (float4*)ppreA, E*32, pobsAs, pobsAh, obsBs_rd, obsBh_rd);
        }
        cudaEventRecord(evA[l], 0);   // hbIn fully consumed
        gemm_ps<false,true><<<gN,256,dynB>>>(
            ppreA, 4, W1ah + l*8192, W1al + l*8192, b1_a + l*128, ptA, N,
            pstatsA, nullptr, nullptr);
        k_bn_finalize<<<1,128>>>(pstatsA, bng_a + l*128, bnb_a + l*128, 1.0f/N,
                                 pbnsA, pbnshA);
        if (!last) {
            gemm_ps<true,true><<<gN,256,dynB>>>(
                ptA, 4, W2ah + l*8192, W2al + l*8192, b2_a + l*128, outAtom, N,
                pstatsA, pbnsA, pbnshA);
            k_bn_finalize<<<1,128>>>(pstatsA, obng_a + l*128, obnb_a + l*128, 1.0f/N,
                                     pobsAs, pobsAh);
        } else {
            gemm_ps<true,false><<<gN,256,dynB>>>(
                ptA, 4, W2ah + l*8192, W2al + l*8192, b2_a + l*128, outAtom, N,
                nullptr, pbnsA, pbnshA);
        }

        // ================= bond chain (stream s1) =================
        k_bond_embed<true><<<blks(E*32),256,0,s1>>>(pTb + (long)(l+1)*8*TBL, eaf, eint,
            bond_tables + (long)(l+1)*3*12*128, pbbond + (l+1)*128,
            (float4*)pembB, (float4*)ppreB, eps_g + l, E*32);
        k_ang_scatter<<<blks(A*32),256,0,s1>>>(pTa + (long)l*TBL, ba_W_rest + l*5*128,
            pbang + l*128, eab, srcb, dstb, (const float4*)pembB, (float4*)ppreB, A*32);
        gemm_ps<false,true><<<gE,256,dynB,s1>>>(
            ppreB, 4, W1gh + l*8192, W1gl + l*8192, b1_g + l*128, ptB, E,
            pstatsB, nullptr, nullptr);
        k_bn_finalize<<<1,128,0,s1>>>(pstatsB, bng_g + l*128, bnb_g + l*128, 1.0f/E,
                                      pbnsB, pbnshB);
        // W2 overwrites the buffer read by atom scatter of layer l-1
        if (l > 0) cudaStreamWaitEvent(s1, evA[l-1], 0);
        if (!last) {
            gemm_ps<true,true><<<gE,256,dynB,s1>>>(
                ptB, 4, W2gh + l*8192, W2gl + l*8192, b2_g + l*128, hbOut, E,
                pstatsB, pbnsB, pbnshB);
            k_bn_finalize<<<1,128,0,s1>>>(pstatsB, obng_ba + l*128, obnb_ba + l*128, 1.0f/E,
                                          obsBs_wr, obsBh_wr);
        } else {
            gemm_ps<true,false><<<gE,256,dynB,s1>>>(
                ptB, 4, W2gh + l*8192, W2gl + l*8192, b2_g + l*128, hbOut, E,
                nullptr, pbnsB, pbnshB);
        }
        cudaEventRecord(evB[l], s1);
    }

    // final join: outB written on s1
    cudaStreamWaitEvent(0, evB[LL-1], 0);
    k_noop<<<1,1>>>();

    cudaEventDestroy(evF);
    for (int l = 0; l < LL; ++l) {
        cudaEventDestroy(evB[l]);
        cudaEventDestroy(evA[l]);
    }
    cudaStreamDestroy(s1);
}

// round 17
// speedup vs baseline: 1.3582x; 1.3176x over previous
#include <cuda_runtime.h>
#include <cuda_bf16.h>
#include <cuda_fp16.h>
#include <math.h>

#define NN 100000
#define EE 200000
#define AA 400000
#define LL 5
#define GRID_N 2048   // lerp grid intervals over [0,1]

// ---------------- scratch (static device globals; no runtime alloc) ----------
__device__ float g_h[NN*128];
__device__ float g_hb[EE*128];
__device__ float g_preA[NN*128];
__device__ float g_preB[EE*128];
__device__ float g_t[EE*128];
__device__ float g_embB[EE*128];

// pair-packed bf16 weights for the MLP GEMMs
__device__ unsigned g_W1ah[LL*64*128], g_W1al[LL*64*128];
__device__ unsigned g_W2ah[LL*64*128], g_W2al[LL*64*128];
__device__ unsigned g_W1gh[LL*64*128], g_W1gl[LL*64*128];
__device__ unsigned g_W2gh[LL*64*128], g_W2gl[LL*64*128];

// fp32 interpolation tables (build staging)
__device__ float g_Tb[(LL+1)*8*(GRID_N+1)*128];
__device__ float g_Ta[LL*(GRID_N+1)*128];
// fp16 pair-packed tables: entry[g][c] = half2(T[g][c], T[g+1][c])
__device__ __half2 g_Tb16[(LL+1)*8*GRID_N*128];
__device__ __half2 g_Ta16[LL*GRID_N*128];

__device__ float g_bang[LL*128];
__device__ float g_bbond[(LL+1)*128];
__device__ float g_stats[256];
__device__ float g_bns[128];
__device__ float g_bnsh[128];
__device__ float g_obsAs[128], g_obsAh[128];
__device__ float g_obsBs[128], g_obsBh[128];

__constant__ double c_bf_start[8] = {0.0,0.0,3.0,0.0,0.0,0.0,0.0,0.0};
__constant__ double c_bf_step[8]  = {0.1,0.05,0.3,0.05,0.05,0.05,0.5,0.05};
__constant__ int    c_bf_cnt[8]   = {20,20,30,20,20,20,20,20};
__constant__ float  c_bf_g[8]     = {10.f,1.f,1.f,1.f,1.f,1.f,2.f,1.f};

// ---------------- helpers -----------------------------------------------------
__device__ __forceinline__ void split_pack(float x, float y, unsigned &hi, unsigned &lo)
{
    __nv_bfloat16 bx = __float2bfloat16_rn(x);
    __nv_bfloat16 by = __float2bfloat16_rn(y);
    float rx = x - __bfloat162float(bx);
    float ry = y - __bfloat162float(by);
    __nv_bfloat16 brx = __float2bfloat16_rn(rx);
    __nv_bfloat16 bry = __float2bfloat16_rn(ry);
    hi = ((unsigned)__bfloat16_as_ushort(by) << 16) | __bfloat16_as_ushort(bx);
    lo = ((unsigned)__bfloat16_as_ushort(bry) << 16) | __bfloat16_as_ushort(brx);
}

#define MMA_BF16(d, a0,a1,a2,a3, b0,b1) \
    asm volatile( \
        "mma.sync.aligned.m16n8k16.row.col.f32.bf16.bf16.f32 " \
        "{%0,%1,%2,%3}, {%4,%5,%6,%7}, {%8,%9}, {%0,%1,%2,%3};" \
        : "+f"(d[0]), "+f"(d[1]), "+f"(d[2]), "+f"(d[3]) \
        : "r"(a0), "r"(a1), "r"(a2), "r"(a3), "r"(b0), "r"(b1))

// ---------------- persistent bf16x3 mma GEMM (pipelined, 2 CTA/SM) -----------
template<bool TRANSFORM, bool STATS>
__global__ void __launch_bounds__(256,2) gemm_ps(
    const float* __restrict__ Aop, int chunks,
    const unsigned* __restrict__ Wph, const unsigned* __restrict__ Wpl,
    const float* __restrict__ bias, float* __restrict__ Y, int M,
    float* __restrict__ stats, const float* __restrict__ sc, const float* __restrict__ sh)
{
    extern __shared__ unsigned dyn[];
    unsigned* Wsh   = dyn;
    unsigned* Wsl   = dyn + chunks*2048;
    unsigned* Abase = dyn + 2*chunks*2048;
    __shared__ float sSum[128], sSq[128];

    const int tid  = threadIdx.x;
    const int lane = tid & 31;
    const int warp = tid >> 5;
    const int wm = warp >> 2;
    const int wn = warp & 3;

    if (STATS && tid < 128) { sSum[tid] = 0.f; sSq[tid] = 0.f; }

    for (int i = tid; i < chunks*512; i += 256) {
        int c    = i >> 9;
        int j    = i & 511;
        int kpl  = j >> 5;
        int col0 = (j & 31) << 2;
        int kp   = c*16 + kpl;
        uint4 vh = *(const uint4*)(Wph + kp*128 + col0);
        uint4 vl = *(const uint4*)(Wpl + kp*128 + col0);
        int s = kpl >> 3, pp = kpl & 7, tig = pp & 3, reg = pp >> 2;
        int nt = col0 >> 3;
        int b0 = ((((nt<<1)+s)<<5) + ((col0 & 7)<<2) + tig);
        unsigned* wh = Wsh + c*2048;
        unsigned* wl = Wsl + c*2048;
        wh[(b0+0)*2+reg] = vh.x; wh[(b0+4)*2+reg] = vh.y;
        wh[(b0+8)*2+reg] = vh.z; wh[(b0+12)*2+reg] = vh.w;
        wl[(b0+0)*2+reg] = vl.x; wl[(b0+4)*2+reg] = vl.y;
        wl[(b0+8)*2+reg] = vl.z; wl[(b0+12)*2+reg] = vl.w;
    }

    const int colq = (lane & 3) << 1;
    float bv[4][2];
#pragma unroll
    for (int ni = 0; ni < 4; ++ni) {
        int c = wn*32 + ni*8 + colq;
        bv[ni][0] = bias[c];
        bv[ni][1] = bias[c+1];
    }
    float cs[4][2], cq[4][2];
#pragma unroll
    for (int ni=0;ni<4;++ni){ cs[ni][0]=cs[ni][1]=0.f; cq[ni][0]=cq[ni][1]=0.f; }

    const int row0 = tid >> 2,        q0 = tid & 3;
    const int row1 = (tid+256) >> 2,  q1 = (tid+256) & 3;

    float4 pf[2][2];

    const int ntiles = (M + 127) >> 7;
    for (int tile = blockIdx.x; tile < ntiles; tile += gridDim.x) {
        const int m0 = tile << 7;

        float acc[4][4][4];
#pragma unroll
        for (int i=0;i<4;++i)
#pragma unroll
            for (int j=0;j<4;++j)
#pragma unroll
                for (int r=0;r<4;++r) acc[i][j][r] = 0.f;

        auto load_chunk = [&](int c) {
#pragma unroll
            for (int it = 0; it < 2; ++it) {
                int row = it ? row1 : row0, q = it ? q1 : q0;
                int grow = m0 + row;
                pf[it][0] = make_float4(0.f,0.f,0.f,0.f);
                pf[it][1] = pf[it][0];
                if (grow < M) {
                    long off = (long)grow*128 + c*32 + (q << 3);
                    pf[it][0] = *(const float4*)(Aop + off);
                    pf[it][1] = *(const float4*)(Aop + off + 4);
                }
            }
        };
        auto store_chunk = [&](int c) {
            unsigned* Ash = Abase + (c & 1)*4096;
            unsigned* Asl = Ash + 2048;
#pragma unroll
            for (int it = 0; it < 2; ++it) {
                int row = it ? row1 : row0, q = it ? q1 : q0;
                uint4 vh, vl;
                float4 u0 = pf[it][0], u1 = pf[it][1];
                if (TRANSFORM) {
                    int gk = c*32 + (q << 3);
                    float4 s0 = *(const float4*)(sc+gk), s1 = *(const float4*)(sc+gk+4);
                    float4 t0 = *(const float4*)(sh+gk), t1 = *(const float4*)(sh+gk+4);
                    u0.x = fmaxf(fmaf(u0.x,s0.x,t0.x),0.f);
                    u0.y = fmaxf(fmaf(u0.y,s0.y,t0.y),0.f);
                    u0.z = fmaxf(fmaf(u0.z,s0.z,t0.z),0.f);
                    u0.w = fmaxf(fmaf(u0.w,s0.w,t0.w),0.f);
                    u1.x = fmaxf(fmaf(u1.x,s1.x,t1.x),0.f);
                    u1.y = fmaxf(fmaf(u1.y,s1.y,t1.y),0.f);
                    u1.z = fmaxf(fmaf(u1.z,s1.z,t1.z),0.f);
                    u1.w = fmaxf(fmaf(u1.w,s1.w,t1.w),0.f);
                }
                split_pack(u0.x,u0.y, vh.x, vl.x);
                split_pack(u0.z,u0.w, vh.y, vl.y);
                split_pack(u1.x,u1.y, vh.z, vl.z);
                split_pack(u1.z,u1.w, vh.w, vl.w);
                int s  = q >> 1, ph = q & 1;
                int reg = ((row >> 3) & 1) | (ph << 1);
                int b0 = ((((row >> 4) << 1) + s) << 5) + ((row & 7) << 2);
                Ash[(b0+0)*4+reg] = vh.x; Ash[(b0+1)*4+reg] = vh.y;
                Ash[(b0+2)*4+reg] = vh.z; Ash[(b0+3)*4+reg] = vh.w;
                Asl[(b0+0)*4+reg] = vl.x; Asl[(b0+1)*4+reg] = vl.y;
                Asl[(b0+2)*4+reg] = vl.z; Asl[(b0+3)*4+reg] = vl.w;
            }
        };

        load_chunk(0);
        store_chunk(0);
        __syncthreads();

        for (int ch = 0; ch < chunks; ++ch) {
            if (ch + 1 < chunks) load_chunk(ch + 1);

            const unsigned* Ash = Abase + (ch & 1)*4096;
            const unsigned* Asl = Ash + 2048;
            const unsigned* wh = Wsh + ch*2048;
            const unsigned* wl = Wsl + ch*2048;
#pragma unroll
            for (int s = 0; s < 2; ++s) {
                unsigned bh[4][2], bl[4][2];
#pragma unroll
                for (int ni = 0; ni < 4; ++ni) {
                    int base = (((((wn*4 + ni) << 1) + s) << 5) | lane) << 1;
                    uint2 fh = *(const uint2*)&wh[base];
                    uint2 fl = *(const uint2*)&wl[base];
                    bh[ni][0]=fh.x; bh[ni][1]=fh.y;
                    bl[ni][0]=fl.x; bl[ni][1]=fl.y;
                }
#pragma unroll
                for (int mi = 0; mi < 4; ++mi) {
                    int base = (((((wm*4 + mi) << 1) + s) << 5) | lane) << 2;
                    uint4 ah = *(const uint4*)&Ash[base];
                    uint4 al = *(const uint4*)&Asl[base];
#pragma unroll
                    for (int ni = 0; ni < 4; ++ni) {
                        MMA_BF16(acc[mi][ni], ah.x, ah.y, ah.z, ah.w, bh[ni][0], bh[ni][1]);
                        MMA_BF16(acc[mi][ni], ah.x, ah.y, ah.z, ah.w, bl[ni][0], bl[ni][1]);
                        MMA_BF16(acc[mi][ni], al.x, al.y, al.z, al.w, bh[ni][0], bh[ni][1]);
                    }
                }
            }

            if (ch + 1 < chunks) {
                store_chunk(ch + 1);
                __syncthreads();
            }
        }

#pragma unroll
        for (int mi = 0; mi < 4; ++mi) {
#pragma unroll
            for (int half = 0; half < 2; ++half) {
                int row = m0 + wm*64 + mi*16 + (lane >> 2) + half*8;
                if (row < M) {
#pragma unroll
                    for (int ni = 0; ni < 4; ++ni) {
                        int c = wn*32 + ni*8 + colq;
                        float y0 = acc[mi][ni][half*2+0] + bv[ni][0];
                        float y1 = acc[mi][ni][half*2+1] + bv[ni][1];
                        *(float2*)(Y + (long)row*128 + c) = make_float2(y0, y1);
                        if (STATS) {
                            cs[ni][0] += y0; cs[ni][1] += y1;
                            cq[ni][0] += y0*y0; cq[ni][1] += y1*y1;
                        }
                    }
                }
            }
        }
    }

    if (STATS) {
        __syncthreads();
#pragma unroll
        for (int ni = 0; ni < 4; ++ni) {
            int c = wn*32 + ni*8 + colq;
            atomicAdd(&sSum[c],   cs[ni][0]);
            atomicAdd(&sSum[c+1], cs[ni][1]);
            atomicAdd(&sSq[c],    cq[ni][0]);
            atomicAdd(&sSq[c+1],  cq[ni][1]);
        }
        __syncthreads();
        if (tid < 128) {
            atomicAdd(&stats[tid],     sSum[tid]);
            atomicAdd(&stats[128+tid], sSq[tid]);
        }
    }
}

// weight transpose+split
__global__ void k_splitW(const float* __restrict__ W, unsigned* __restrict__ dh,
                         unsigned* __restrict__ dl, int K, int Kp2, int total)
{
    int idx = blockIdx.x*blockDim.x + threadIdx.x;
    if (idx >= total) return;
    int b   = idx / (Kp2*128);
    int rem = idx - b*Kp2*128;
    int kp  = rem >> 7;
    int n   = rem & 127;
    int k0 = kp*2, k1 = k0 + 1;
    float v0 = (k0 < K) ? W[(long)b*K*128 + (long)k0*128 + n] : 0.f;
    float v1 = (k1 < K) ? W[(long)b*K*128 + (long)k1*128 + n] : 0.f;
    unsigned h, l;
    split_pack(v0, v1, h, l);
    dh[idx] = h; dl[idx] = l;
}

// ---------------- interpolation table builders -------------------------------
__global__ void k_build_bond(const float* __restrict__ bfW, float* __restrict__ Tb)
{
    __shared__ float sW[30*128];
    __shared__ float sE[32][32];
    int lf  = blockIdx.y;
    int f   = lf & 7;
    int col = threadIdx.x;
    for (int c = 0; c < 30; ++c) sW[c*128+col] = bfW[((long)lf*30 + c)*128 + col];
    int g0 = blockIdx.x * 32;
    for (int i = col; i < 32*30; i += 128) {
        int gl = i / 30, c = i - gl*30;
        int g = g0 + gl;
        float v = 0.f;
        if (g <= GRID_N && c < c_bf_cnt[f]) {
            float x = (float)g / (float)GRID_N;
            float ctr = (float)(c_bf_start[f] + c_bf_step[f]*(double)c);
            float d = x - ctr;
            v = expf(-c_bf_g[f]*d*d);
        }
        sE[gl][c] = v;
    }
    __syncthreads();
    for (int gl = 0; gl < 32; ++gl) {
        int g = g0 + gl;
        if (g > GRID_N) break;
        float acc = 0.f;
#pragma unroll
        for (int c = 0; c < 30; ++c) acc = fmaf(sE[gl][c], sW[c*128+col], acc);
        Tb[((long)lf*(GRID_N+1) + g)*128 + col] = acc;
    }
}

__global__ void k_build_ang(const float* __restrict__ Wa, float* __restrict__ Ta)
{
    __shared__ float sW[32*128];
    __shared__ float sE[32][33];
    int l   = blockIdx.y;
    int col = threadIdx.x;
    for (int c = 0; c < 32; ++c) sW[c*128+col] = Wa[((long)l*32 + c)*128 + col];
    int g0 = blockIdx.x * 32;
    for (int i = col; i < 32*32; i += 128) {
        int gl = i >> 5, c = i & 31;
        int g = g0 + gl;
        float v = 0.f;
        if (g <= GRID_N) {
            float x = (float)g / (float)GRID_N;
            float ctr = (float)((double)c * 0.1);
            float d = x - ctr;
            v = expf(-10.f*d*d);
        }
        sE[gl][c] = v;
    }
    __syncthreads();
    for (int gl = 0; gl < 32; ++gl) {
        int g = g0 + gl;
        if (g > GRID_N) break;
        float acc = 0.f;
#pragma unroll
        for (int c = 0; c < 32; ++c) acc = fmaf(sE[gl][c], sW[c*128+col], acc);
        Ta[((long)l*(GRID_N+1) + g)*128 + col] = acc;
    }
}

// convert fp32 tables -> fp16 pair-packed (row g holds (T[g], T[g+1]))
__global__ void k_cvt_pairs(const float* __restrict__ T, __half2* __restrict__ T16,
                            int nBatch, long total)
{
    long idx = (long)blockIdx.x*blockDim.x + threadIdx.x;
    if (idx >= total) return;
    long perB = (long)GRID_N * 128;
    int  b    = (int)(idx / perB);
    long rem  = idx - (long)b*perB;
    int  g    = (int)(rem >> 7);
    int  c    = (int)(rem & 127);
    const float* base = T + ((long)b*(GRID_N+1) + g)*128 + c;
    T16[idx] = __floats2half2_rn(base[0], base[128]);
}

// ---------------- bond embed via fp16 pair tables ----------------------------
template<bool WRITE_PRE>
__global__ void __launch_bounds__(256) k_bond_embed(
    const __half2* __restrict__ Tb16,
    const float* __restrict__ xf,
    const int* __restrict__ eint,
    const float* __restrict__ etab,
    const float* __restrict__ bias,
    float4* __restrict__ out, float4* __restrict__ pre,
    const float* __restrict__ epsP, int E32)
{
    int t = blockIdx.x*blockDim.x + threadIdx.x;
    if (t >= E32) return;
    int e = t >> 5, cg = t & 31, lane = threadIdx.x & 31;

    float xs = (lane < 8) ? xf[e*8 + lane] : 0.f;
    int   ii = (lane < 3) ? eint[e*3 + lane] : 0;

    float4 acc = *((const float4*)bias + cg);
#pragma unroll
    for (int f2 = 0; f2 < 3; ++f2) {
        int idx = __shfl_sync(0xffffffffu, ii, f2);
        float4 v = *((const float4*)(etab + (long)(f2*12 + idx)*128) + cg);
        acc.x += v.x; acc.y += v.y; acc.z += v.z; acc.w += v.w;
    }
#pragma unroll
    for (int f = 0; f < 8; ++f) {
        float x = __shfl_sync(0xffffffffu, xs, f);
        float u = x * (float)GRID_N;
        int gi = (int)u;
        gi = gi < 0 ? 0 : (gi > GRID_N-1 ? GRID_N-1 : gi);
        float fr = u - (float)gi;
        const __half2* base = Tb16 + ((long)f*GRID_N + gi)*128;
        uint4 pk = *((const uint4*)base + cg);
        __half2 h0 = *(__half2*)&pk.x, h1 = *(__half2*)&pk.y;
        __half2 h2 = *(__half2*)&pk.z, h3 = *(__half2*)&pk.w;
        float a0 = __low2float(h0), b0 = __high2float(h0);
        float a1 = __low2float(h1), b1 = __high2float(h1);
        float a2 = __low2float(h2), b2 = __high2float(h2);
        float a3 = __low2float(h3), b3 = __high2float(h3);
        acc.x += a0 + fr*(b0 - a0);
        acc.y += a1 + fr*(b1 - a1);
        acc.z += a2 + fr*(b2 - a2);
        acc.w += a3 + fr*(b3 - a3);
    }
    out[t] = acc;
    if (WRITE_PRE) {
        float ep = 1.f + *epsP;
        float4 p;
        p.x = acc.x*ep; p.y = acc.y*ep; p.z = acc.z*ep; p.w = acc.w*ep;
        pre[t] = p;
    }
}

// ---------------- angle embed (fp16 pair table) + rank-5 + fused scatter -----
__global__ void __launch_bounds__(256) k_ang_scatter(
    const __half2* __restrict__ Ta16,
    const float* __restrict__ Wr,
    const float* __restrict__ bias,
    const float* __restrict__ xa,
    const int* __restrict__ srcb, const int* __restrict__ dstb,
    const float4* __restrict__ X, float4* __restrict__ P,
    int A32)
{
    int t = blockIdx.x*blockDim.x + threadIdx.x;
    if (t >= A32) return;
    int a = t >> 5, cg = t & 31, lane = threadIdx.x & 31;

    float xs = (lane < 6) ? xa[a*6 + lane] : 0.f;
    float x0 = __shfl_sync(0xffffffffu, xs, 0);

    float u = x0 * (float)GRID_N;
    int gi = (int)u;
    gi = gi < 0 ? 0 : (gi > GRID_N-1 ? GRID_N-1 : gi);
    float fr = u - (float)gi;

    float4 acc = *((const float4*)bias + cg);
    {
        const __half2* base = Ta16 + (long)gi*128;
        uint4 pk = *((const uint4*)base + cg);
        __half2 h0 = *(__half2*)&pk.x, h1 = *(__half2*)&pk.y;
        __half2 h2 = *(__half2*)&pk.z, h3 = *(__half2*)&pk.w;
        float a0 = __low2float(h0), b0 = __high2float(h0);
        float a1 = __low2float(h1), b1 = __high2float(h1);
        float a2 = __low2float(h2), b2 = __high2float(h2);
        float a3 = __low2float(h3), b3 = __high2float(h3);
        acc.x += a0 + fr*(b0 - a0);
        acc.y += a1 + fr*(b1 - a1);
        acc.z += a2 + fr*(b2 - a2);
        acc.w += a3 + fr*(b3 - a3);
    }
#pragma unroll
    for (int j = 0; j < 5; ++j) {
        float rj = __shfl_sync(0xffffffffu, xs, j + 1);
        float4 w = *((const float4*)(Wr + j*128) + cg);
        acc.x = fmaf(rj, w.x, acc.x);
        acc.y = fmaf(rj, w.y, acc.y);
        acc.z = fmaf(rj, w.z, acc.z);
        acc.w = fmaf(rj, w.w, acc.w);
    }
    int s = srcb[a], d = dstb[a];
    float4 xv = X[(long)s*32 + cg];
    float4 m;
    m.x = fmaxf(xv.x + acc.x, 0.f);
    m.y = fmaxf(xv.y + acc.y, 0.f);
    m.z = fmaxf(xv.z + acc.z, 0.f);
    m.w = fmaxf(xv.w + acc.w, 0.f);
#if defined(__CUDA_ARCH__) && (__CUDA_ARCH__ >= 900)
    atomicAdd(&P[(long)d*32 + cg], m);
#else
    float* p = (float*)&P[(long)d*32 + cg];
    atomicAdd(p+0, m.x); atomicAdd(p+1, m.y);
    atomicAdd(p+2, m.z); atomicAdd(p+3, m.w);
#endif
}

// ---------------- GIN helpers -----------------------------------------------
template<bool TR>
__global__ void k_init_pre(const float4* __restrict__ X, float4* __restrict__ P,
                           int M32, const float* __restrict__ epsP,
                           const float* __restrict__ sc, const float* __restrict__ sh)
{
    int t = blockIdx.x*blockDim.x + threadIdx.x;
    if (t >= M32) return;
    float e = 1.f + *epsP;
    float4 x = X[t];
    if (TR) {
        int cb = (t & 31) << 2;
        x.x = fmaxf(fmaf(x.x, sc[cb+0], sh[cb+0]), 0.f);
        x.y = fmaxf(fmaf(x.y, sc[cb+1], sh[cb+1]), 0.f);
        x.z = fmaxf(fmaf(x.z, sc[cb+2], sh[cb+2]), 0.f);
        x.w = fmaxf(fmaf(x.w, sc[cb+3], sh[cb+3]), 0.f);
    }
    x.x *= e; x.y *= e; x.z *= e; x.w *= e;
    P[t] = x;
}

template<bool TR>
__global__ void k_scatter(const float4* __restrict__ X, const float4* __restrict__ EA,
                          const int* __restrict__ src, const int* __restrict__ dst,
                          float4* __restrict__ P, int E32,
                          const float* __restrict__ scx, const float* __restrict__ shx,
                          const float* __restrict__ sce, const float* __restrict__ she)
{
    int t = blockIdx.x*blockDim.x + threadIdx.x;
    if (t >= E32) return;
    int e = t >> 5, l = t & 31;
    int s = src[e], d = dst[e];
    float4 x = X[s*32 + l];
    float4 a = EA[(e<<5) + l];
    if (TR) {
        int cb = l << 2;
        x.x = fmaxf(fmaf(x.x, scx[cb+0], shx[cb+0]), 0.f);
        x.y = fmaxf(fmaf(x.y, scx[cb+1], shx[cb+1]), 0.f);
        x.z = fmaxf(fmaf(x.z, scx[cb+2], shx[cb+2]), 0.f);
        x.w = fmaxf(fmaf(x.w, scx[cb+3], shx[cb+3]), 0.f);
        a.x = fmaxf(fmaf(a.x, sce[cb+0], she[cb+0]), 0.f);
        a.y = fmaxf(fmaf(a.y, sce[cb+1], she[cb+1]), 0.f);
        a.z = fmaxf(fmaf(a.z, sce[cb+2], she[cb+2]), 0.f);
        a.w = fmaxf(fmaf(a.w, sce[cb+3], she[cb+3]), 0.f);
    }
    float4 m;
    m.x = fmaxf(x.x + a.x, 0.f);
    m.y = fmaxf(x.y + a.y, 0.f);
    m.z = fmaxf(x.z + a.z, 0.f);
    m.w = fmaxf(x.w + a.w, 0.f);
#if defined(__CUDA_ARCH__) && (__CUDA_ARCH__ >= 900)
    atomicAdd(&P[d*32 + l], m);
#else
    float* p = (float*)&P[d*32 + l];
    atomicAdd(p+0, m.x); atomicAdd(p+1, m.y);
    atomicAdd(p+2, m.z); atomicAdd(p+3, m.w);
#endif
}

__global__ void k_bn_finalize(float* __restrict__ stats, const float* __restrict__ g,
                              const float* __restrict__ b, float invM,
                              float* __restrict__ oscale, float* __restrict__ oshift)
{
    int c = threadIdx.x;
    float mu  = stats[c] * invM;
    float var = stats[128+c] * invM - mu*mu;
    float rs  = rsqrtf(var + 1e-5f);
    float scv = g[c] * rs;
    oscale[c] = scv;
    oshift[c] = b[c] - mu*scv;
    stats[c] = 0.f;
    stats[128+c] = 0.f;
}

// ---------------- misc --------------------------------------------------------
__global__ void k_atom_embed(const int* __restrict__ xa, const float4* __restrict__ tab,
                             float4* __restrict__ H, int N32)
{
    int t = blockIdx.x*blockDim.x + threadIdx.x;
    if (t >= N32) return;
    int n = t >> 5, l = t & 31;
    float4 s = make_float4(0.f,0.f,0.f,0.f);
#pragma unroll
    for (int f=0; f<9; ++f) {
        int idx = xa[n*9 + f];
        float4 v = tab[(f*124 + idx)*32 + l];
        s.x += v.x; s.y += v.y; s.z += v.z; s.w += v.w;
    }
    H[t] = s;
}

__global__ void k_pack(const float* __restrict__ baBang, const float* __restrict__ baBrest,
                       const float* __restrict__ bfb,
                       float* __restrict__ bang, float* __restrict__ bbond)
{
    int c = threadIdx.x;
    for (int l=0; l<LL; ++l)
        bang[l*128 + c] = baBang[l*128 + c] + baBrest[l*128 + c];
    for (int l=0; l<=LL; ++l) {
        float s = 0.f;
        for (int f=0; f<8; ++f) s += bfb[(l*8 + f)*128 + c];
        bbond[l*128 + c] = s;
    }
}

// ---------------- launcher ---------------------------------------------------
extern "C" void kernel_launch(void* const* d_in, const int* in_sizes, int n_in,
                              void* d_out, int out_size)
{
    const int N = NN, E = EE, A = AA;

    const int*   x_atom      = (const int*)  d_in[0];
    const int*   edge_index  = (const int*)  d_in[1];
    const int*   eint        = (const int*)  d_in[2];
    const int*   eiba        = (const int*)  d_in[3];
    const float* eaf         = (const float*)d_in[4];
    const float* eab         = (const float*)d_in[5];
    const float* atom_tables = (const float*)d_in[6];
    const float* bond_tables = (const float*)d_in[7];
    const float* bf_W        = (const float*)d_in[8];
    const float* bf_b        = (const float*)d_in[9];
    const float* ba_W_ang    = (const float*)d_in[10];
    const float* ba_b_ang    = (const float*)d_in[11];
    const float* ba_W_rest   = (const float*)d_in[12];
    const float* ba_b_rest   = (const float*)d_in[13];
    const float* eps_a       = (const float*)d_in[14];
    const float* W1_a        = (const float*)d_in[15];
    const float* b1_a        = (const float*)d_in[16];
    const float* bng_a       = (const float*)d_in[17];
    const float* bnb_a       = (const float*)d_in[18];
    const float* W2_a        = (const float*)d_in[19];
    const float* b2_a        = (const float*)d_in[20];
    const float* eps_g       = (const float*)d_in[21];
    const float* W1_g        = (const float*)d_in[22];
    const float* b1_g        = (const float*)d_in[23];
    const float* bng_g       = (const float*)d_in[24];
    const float* bnb_g       = (const float*)d_in[25];
    const float* W2_g        = (const float*)d_in[26];
    const float* b2_g        = (const float*)d_in[27];
    const float* obng_a      = (const float*)d_in[28];
    const float* obnb_a      = (const float*)d_in[29];
    const float* obng_ba     = (const float*)d_in[30];
    const float* obnb_ba     = (const float*)d_in[31];

    const int* src  = edge_index;
    const int* dst  = edge_index + E;
    const int* srcb = eiba;
    const int* dstb = eiba + A;

    float *ph, *phb, *ppreA, *ppreB, *pt, *pembB;
    float *pbang, *pbbond, *pstats, *pbns, *pbnsh;
    float *pobsAs, *pobsAh, *pobsBs, *pobsBh;
    float *pTb, *pTa;
    __half2 *pTb16, *pTa16;
    unsigned *W1ah,*W1al,*W2ah,*W2al,*W1gh,*W1gl,*W2gh,*W2gl;
    cudaGetSymbolAddress((void**)&ph,    g_h);
    cudaGetSymbolAddress((void**)&phb,   g_hb);
    cudaGetSymbolAddress((void**)&ppreA, g_preA);
    cudaGetSymbolAddress((void**)&ppreB, g_preB);
    cudaGetSymbolAddress((void**)&pt,    g_t);
    cudaGetSymbolAddress((void**)&pembB, g_embB);
    cudaGetSymbolAddress((void**)&pbang, g_bang);
    cudaGetSymbolAddress((void**)&pbbond,g_bbond);
    cudaGetSymbolAddress((void**)&pstats,g_stats);
    cudaGetSymbolAddress((void**)&pbns,  g_bns);
    cudaGetSymbolAddress((void**)&pbnsh, g_bnsh);
    cudaGetSymbolAddress((void**)&pobsAs,g_obsAs);
    cudaGetSymbolAddress((void**)&pobsAh,g_obsAh);
    cudaGetSymbolAddress((void**)&pobsBs,g_obsBs);
    cudaGetSymbolAddress((void**)&pobsBh,g_obsBh);
    cudaGetSymbolAddress((void**)&pTb,   g_Tb);
    cudaGetSymbolAddress((void**)&pTa,   g_Ta);
    cudaGetSymbolAddress((void**)&pTb16, g_Tb16);
    cudaGetSymbolAddress((void**)&pTa16, g_Ta16);
    cudaGetSymbolAddress((void**)&W1ah,  g_W1ah); cudaGetSymbolAddress((void**)&W1al, g_W1al);
    cudaGetSymbolAddress((void**)&W2ah,  g_W2ah); cudaGetSymbolAddress((void**)&W2al, g_W2al);
    cudaGetSymbolAddress((void**)&W1gh,  g_W1gh); cudaGetSymbolAddress((void**)&W1gl, g_W1gl);
    cudaGetSymbolAddress((void**)&W2gh,  g_W2gh); cudaGetSymbolAddress((void**)&W2gl, g_W2gl);

    float* outA = (float*)d_out;                // final h  [N,128]
    float* outB = (float*)d_out + (long)N*128;  // final h_ba [E,128]

    cudaFuncSetAttribute(gemm_ps<false,true>,  cudaFuncAttributeMaxDynamicSharedMemorySize, 98304);
    cudaFuncSetAttribute(gemm_ps<true,true>,   cudaFuncAttributeMaxDynamicSharedMemorySize, 98304);
    cudaFuncSetAttribute(gemm_ps<true,false>,  cudaFuncAttributeMaxDynamicSharedMemorySize, 98304);

    auto blks = [](int n){ return (n + 255) / 256; };
    const int dynB = 4*16384 + 32768;
    auto gsz  = [](int M){ int t = (M+127)/128; return t < 296 ? t : 296; };
    const long TBL16 = (long)GRID_N*128;

    // secondary stream + fork/join events (no device memory)
    cudaStream_t s1;
    cudaStreamCreateWithFlags(&s1, cudaStreamNonBlocking);
    cudaEvent_t evF, evJ;
    cudaEventCreateWithFlags(&evF, cudaEventDisableTiming);
    cudaEventCreateWithFlags(&evJ, cudaEventDisableTiming);

    // --- one-time (per call) precompute ---
    k_pack<<<1,128>>>(ba_b_ang, ba_b_rest, bf_b, pbang, pbbond);
    k_splitW<<<blks(LL*64*128),256>>>(W1_a, W1ah, W1al, 128, 64, LL*64*128);
    k_splitW<<<blks(LL*64*128),256>>>(W2_a, W2ah, W2al, 128, 64, LL*64*128);
    k_splitW<<<blks(LL*64*128),256>>>(W1_g, W1gh, W1gl, 128, 64, LL*64*128);
    k_splitW<<<blks(LL*64*128),256>>>(W2_g, W2gh, W2gl, 128, 64, LL*64*128);
    {
        dim3 gb((GRID_N+1+31)/32, (LL+1)*8);
        k_build_bond<<<gb,128>>>(bf_W, pTb);
        dim3 ga((GRID_N+1+31)/32, LL);
        k_build_ang<<<ga,128>>>(ba_W_ang, pTa);
        long totB = (long)(LL+1)*8*GRID_N*128;
        long totA = (long)LL*GRID_N*128;
        k_cvt_pairs<<<(int)((totB+255)/256),256>>>(pTb, pTb16, (LL+1)*8, totB);
        k_cvt_pairs<<<(int)((totA+255)/256),256>>>(pTa, pTa16, LL, totA);
    }

    // --- initial embeddings ---
    k_atom_embed<<<blks(N*32),256>>>(x_atom, (const float4*)atom_tables, (float4*)ph, N*32);
    k_bond_embed<false><<<blks(E*32),256>>>(pTb16, eaf, eint, bond_tables, pbbond,
                                            (float4*)phb, nullptr, nullptr, E*32);

    for (int l = 0; l < LL; ++l) {
        const bool last = (l == LL - 1);
        float* outAtom = last ? outA : ph;
        float* outBond = last ? outB : phb;

        // fork: bond-side producers for this layer on s1
        cudaEventRecord(evF, 0);
        cudaStreamWaitEvent(s1, evF, 0);
        k_bond_embed<true><<<blks(E*32),256,0,s1>>>(pTb16 + (long)(l+1)*8*TBL16, eaf, eint,
            bond_tables + (long)(l+1)*3*12*128, pbbond + (l+1)*128,
            (float4*)pembB, (float4*)ppreB, eps_g + l, E*32);
        k_ang_scatter<<<blks(A*32),256,0,s1>>>(pTa16 + (long)l*TBL16, ba_W_rest + l*5*128,
            pbang + l*128, eab, srcb, dstb, (const float4*)pembB, (float4*)ppreB, A*32);
        cudaEventRecord(evJ, s1);

        // ===== atom GIN conv (default stream) =====
        if (l == 0) {
            k_init_pre<false><<<blks(N*32),256>>>((const float4*)ph, (float4*)ppreA, N*32,
                                                  eps_a + l, nullptr, nullptr);
            k_scatter<false><<<blks(E*32),256>>>((const float4*)ph, (const float4*)phb,
                src, dst, (float4*)ppreA, E*32, nullptr, nullptr, nullptr, nullptr);
        } else {
            k_init_pre<true><<<blks(N*32),256>>>((const float4*)ph, (float4*)ppreA, N*32,
                                                 eps_a + l, pobsAs, pobsAh);
            k_scatter<true><<<blks(E*32),256>>>((const float4*)ph, (const float4*)phb,
                src, dst, (float4*)ppreA, E*32, pobsAs, pobsAh, pobsBs, pobsBh);
        }
        gemm_ps<false,true><<<gsz(N),256,dynB>>>(
            ppreA, 4, W1ah + l*8192, W1al + l*8192, b1_a + l*128, pt, N,
            pstats, nullptr, nullptr);
        k_bn_finalize<<<1,128>>>(pstats, bng_a + l*128, bnb_a + l*128, 1.0f/N, pbns, pbnsh);
        if (!last) {
            gemm_ps<true,true><<<gsz(N),256,dynB>>>(
                pt, 4, W2ah + l*8192, W2al + l*8192, b2_a + l*128, outAtom, N,
                pstats, pbns, pbnsh);
            k_bn_finalize<<<1,128>>>(pstats, obng_a + l*128, obnb_a + l*128, 1.0f/N,
                                     pobsAs, pobsAh);
        } else {
            gemm_ps<true,false><<<gsz(N),256,dynB>>>(
                pt, 4, W2ah + l*8192, W2al + l*8192, b2_a + l*128, outAtom, N,
                nullptr, pbns, pbnsh);
        }

        // join: bond pre-buffer ready
        cudaStreamWaitEvent(0, evJ, 0);

        // ===== bond GIN conv (default stream) =====
        gemm_ps<false,true><<<gsz(E),256,dynB>>>(
            ppreB, 4, W1gh + l*8192, W1gl + l*8192, b1_g + l*128, pt, E,
            pstats, nullptr, nullptr);
        k_bn_finalize<<<1,128>>>(pstats, bng_g + l*128, bnb_g + l*128, 1.0f/E, pbns, pbnsh);
        if (!last) {
            gemm_ps<true,true><<<gsz(E),256,dynB>>>(
                pt, 4, W2gh + l*8192, W2gl + l*8192, b2_g + l*128, outBond, E,
                pstats, pbns, pbnsh);
            k_bn_finalize<<<1,128>>>(pstats, obng_ba + l*128, obnb_ba + l*128, 1.0f/E,
                                     pobsBs, pobsBh);
        } else {
            gemm_ps<true,false><<<gsz(E),256,dynB>>>(
                pt, 4, W2gh + l*8192, W2gl + l*8192, b2_g + l*128, outBond, E,
                nullptr, pbns, pbnsh);
        }
    }

    cudaEventDestroy(evF);
    cudaEventDestroy(evJ);
    cudaStreamDestroy(s1);
}